// round 4
// baseline (speedup 1.0000x reference)
#include <cuda_runtime.h>
#include <cuda_bf16.h>
#include <math.h>

#define BATCH 1024
#define DIMD  512
#define DM    1024
#define DI    2048
#define DTR   64
#define DS    16

// ---------------- static scratch (no allocations allowed) ----------------
__device__ float g_cat  [BATCH * DM];     // concat(img, txt)
__device__ float g_x    [BATCH * DM];     // mamba running state
__device__ float g_tmpA [BATCH * DIMD];
__device__ float g_tmpB [BATCH * DIMD];
__device__ float g_h1   [BATCH * DIMD];
__device__ float g_h2   [BATCH * 256];
__device__ float g_xz   [BATCH * (2 * DI)];
__device__ float g_xc   [BATCH * DI];
__device__ float g_dbc  [BATCH * 96];
__device__ float g_delta[BATCH * DI];
__device__ float g_u    [BATCH * DI];
__device__ float g_bcd  [BATCH];
__device__ float g_mo   [BATCH * DM];
__device__ float g_fc   [BATCH * 256];

// ---------------- helpers ----------------
__device__ __forceinline__ float siluf(float x) { return x / (1.f + expf(-x)); }
__device__ __forceinline__ float softplusf_(float x) { return x > 20.f ? x : log1pf(expf(x)); }

enum { EPI_NONE = 0, EPI_RELU = 1, EPI_BIAS = 2, EPI_SOFTPLUS = 3 };

// ---------------- tiled SGEMM: C[M,N] = act(A[M,K] @ W[N,K]^T + bias) ----
// BM=128, BN=64, BK=16, 256 threads, 8x4 per-thread tile.
template <int EPI>
__global__ void __launch_bounds__(256) gemm_nt(
    float* __restrict__ C, const float* __restrict__ A, const float* __restrict__ W,
    const float* __restrict__ bias, int M, int N, int K, int lda)
{
    __shared__ __align__(16) float As[16][132];
    __shared__ __align__(16) float Ws[16][68];

    const int tid = threadIdx.x;
    const int tx = tid & 15;          // n direction
    const int ty = tid >> 4;          // m direction (8 rows each)
    const int lr = tid >> 2;          // 0..63 load row
    const int lk = (tid & 3) << 2;    // 0,4,8,12 load k

    const int mBase = blockIdx.y * 128;
    const int nBase = blockIdx.x * 64;

    const float* A0 = A + (size_t)(mBase + lr) * lda + lk;
    const float* A1 = A0 + (size_t)64 * lda;
    const int wRow = nBase + lr;
    const float* W0 = W + (size_t)wRow * K + lk;
    const bool wv = wRow < N;

    float acc[8][4];
#pragma unroll
    for (int i = 0; i < 8; i++)
#pragma unroll
        for (int j = 0; j < 4; j++) acc[i][j] = 0.f;

    for (int k0 = 0; k0 < K; k0 += 16) {
        float4 a0 = *(const float4*)(A0 + k0);
        float4 a1 = *(const float4*)(A1 + k0);
        float4 w0 = wv ? *(const float4*)(W0 + k0) : make_float4(0.f, 0.f, 0.f, 0.f);

        As[lk + 0][lr] = a0.x; As[lk + 1][lr] = a0.y;
        As[lk + 2][lr] = a0.z; As[lk + 3][lr] = a0.w;
        As[lk + 0][lr + 64] = a1.x; As[lk + 1][lr + 64] = a1.y;
        As[lk + 2][lr + 64] = a1.z; As[lk + 3][lr + 64] = a1.w;
        Ws[lk + 0][lr] = w0.x; Ws[lk + 1][lr] = w0.y;
        Ws[lk + 2][lr] = w0.z; Ws[lk + 3][lr] = w0.w;
        __syncthreads();

#pragma unroll
        for (int kk = 0; kk < 16; kk++) {
            float4 av0 = *(const float4*)&As[kk][ty * 8];
            float4 av1 = *(const float4*)&As[kk][ty * 8 + 4];
            float4 wv4 = *(const float4*)&Ws[kk][tx * 4];
            float am[8] = {av0.x, av0.y, av0.z, av0.w, av1.x, av1.y, av1.z, av1.w};
            float wm[4] = {wv4.x, wv4.y, wv4.z, wv4.w};
#pragma unroll
            for (int i = 0; i < 8; i++)
#pragma unroll
                for (int j = 0; j < 4; j++) acc[i][j] = fmaf(am[i], wm[j], acc[i][j]);
        }
        __syncthreads();
    }

    const int col = nBase + tx * 4;
    if (col < N) {
        float4 bv = make_float4(0.f, 0.f, 0.f, 0.f);
        if (EPI != EPI_NONE) bv = *(const float4*)(bias + col);
#pragma unroll
        for (int i = 0; i < 8; i++) {
            const int row = mBase + ty * 8 + i;
            float v0 = acc[i][0], v1 = acc[i][1], v2 = acc[i][2], v3 = acc[i][3];
            if (EPI != EPI_NONE) { v0 += bv.x; v1 += bv.y; v2 += bv.z; v3 += bv.w; }
            if (EPI == EPI_RELU) {
                v0 = fmaxf(v0, 0.f); v1 = fmaxf(v1, 0.f);
                v2 = fmaxf(v2, 0.f); v3 = fmaxf(v3, 0.f);
            }
            if (EPI == EPI_SOFTPLUS) {
                v0 = softplusf_(v0); v1 = softplusf_(v1);
                v2 = softplusf_(v2); v3 = softplusf_(v3);
            }
            *(float4*)(C + (size_t)row * N + col) = make_float4(v0, v1, v2, v3);
        }
    }
}

// ---------------- layernorm (optionally with residual add) ----------------
// one block (128 threads) per row; W in {256, 512, 1024}
__global__ void __launch_bounds__(128) ln_kernel(
    float* __restrict__ out, const float* __restrict__ in, const float* __restrict__ res,
    const float* __restrict__ g, const float* __restrict__ b, int W, int out_stride)
{
    const int row = blockIdx.x;
    const int t = threadIdx.x;
    const int n = W >> 7;  // elems per thread
    const float* ip = in + (size_t)row * W;
    const float* rp = res ? res + (size_t)row * W : nullptr;

    float v[8];
    float s = 0.f, q = 0.f;
    for (int i = 0; i < n; i++) {
        float val = ip[t + i * 128];
        if (rp) val += rp[t + i * 128];
        v[i] = val; s += val; q += val * val;
    }
    __shared__ float ss[4], qs[4];
    for (int o = 16; o > 0; o >>= 1) {
        s += __shfl_down_sync(0xffffffffu, s, o);
        q += __shfl_down_sync(0xffffffffu, q, o);
    }
    if ((t & 31) == 0) { ss[t >> 5] = s; qs[t >> 5] = q; }
    __syncthreads();
    __shared__ float mean_s, rstd_s;
    if (t == 0) {
        float S = ss[0] + ss[1] + ss[2] + ss[3];
        float Q = qs[0] + qs[1] + qs[2] + qs[3];
        float m = S / (float)W;
        float var = Q / (float)W - m * m;
        mean_s = m;
        rstd_s = rsqrtf(var + 1e-5f);
    }
    __syncthreads();
    const float m = mean_s, r = rstd_s;
    float* op = out + (size_t)row * out_stride;
    for (int i = 0; i < n; i++) {
        int idx = t + i * 128;
        op[idx] = (v[i] - m) * r * g[idx] + b[idx];
    }
}

// ---------------- gate head: logits(2) -> softmax -> scale cat into x ----
__global__ void __launch_bounds__(128) gate_kernel(
    float* __restrict__ x, float* __restrict__ gate_out, const float* __restrict__ h2,
    const float* __restrict__ cat, const float* __restrict__ w3, const float* __restrict__ b3)
{
    const int bi = blockIdx.x;
    const int t = threadIdx.x;
    const float* h = h2 + (size_t)bi * 256;
    float p0 = 0.f, p1 = 0.f;
    for (int i = t; i < 256; i += 128) {
        float hv = h[i];
        p0 += hv * w3[i];
        p1 += hv * w3[256 + i];
    }
    __shared__ float s0[4], s1[4];
    for (int o = 16; o > 0; o >>= 1) {
        p0 += __shfl_down_sync(0xffffffffu, p0, o);
        p1 += __shfl_down_sync(0xffffffffu, p1, o);
    }
    if ((t & 31) == 0) { s0[t >> 5] = p0; s1[t >> 5] = p1; }
    __syncthreads();
    __shared__ float g0s, g1s;
    if (t == 0) {
        float l0 = s0[0] + s0[1] + s0[2] + s0[3] + b3[0];
        float l1 = s1[0] + s1[1] + s1[2] + s1[3] + b3[1];
        float mx = fmaxf(l0, l1);
        float e0 = expf(l0 - mx), e1 = expf(l1 - mx);
        float inv = 1.f / (e0 + e1);
        g0s = e0 * inv; g1s = e1 * inv;
        gate_out[bi * 2 + 0] = g0s;
        gate_out[bi * 2 + 1] = g1s;
    }
    __syncthreads();
    const float g0 = g0s, g1 = g1s;
    const float* c = cat + (size_t)bi * DM;
    float* xo = x + (size_t)bi * DM;
    for (int i = t; i < DM; i += 128) xo[i] = c[i] * (i < DIMD ? g0 : g1);
}

// ---------------- conv (L=1 -> single tap) + silu ----------------
__global__ void __launch_bounds__(256) conv_silu_kernel(
    float* __restrict__ xc, const float* __restrict__ xz,
    const float* __restrict__ cw, const float* __restrict__ cb)
{
    int idx = blockIdx.x * 256 + threadIdx.x;   // B * DI
    int d = idx & (DI - 1);
    int bi = idx >> 11;
    float v = xz[(size_t)bi * (2 * DI) + d] * cw[d * 4 + 3] + cb[d];
    xc[idx] = siluf(v);
}

// ---------------- per-batch Bc . Cc ----------------
__global__ void bcdot_kernel(float* __restrict__ bcd, const float* __restrict__ dbc)
{
    int bi = blockIdx.x * blockDim.x + threadIdx.x;
    if (bi < BATCH) {
        const float* p = dbc + (size_t)bi * 96;
        float s = 0.f;
#pragma unroll
        for (int i = 0; i < DS; i++) s += p[64 + i] * p[80 + i];
        bcd[bi] = s;
    }
}

// ---------------- ssm collapse (L=1) + silu(z) gating ----------------
// u = xc * (delta * (Bc.Cc) + D) * silu(z)
__global__ void __launch_bounds__(256) ssm_kernel(
    float* __restrict__ u, const float* __restrict__ delta, const float* __restrict__ xc,
    const float* __restrict__ xz, const float* __restrict__ bcd, const float* __restrict__ Dp)
{
    int idx = blockIdx.x * 256 + threadIdx.x;
    int d = idx & (DI - 1);
    int bi = idx >> 11;
    float z = xz[(size_t)bi * (2 * DI) + DI + d];
    float y = xc[idx] * (delta[idx] * bcd[bi] + Dp[d]);
    u[idx] = y * siluf(z);
}

// ---------------- launch ----------------
static inline dim3 ggrid(int M, int N) { return dim3((N + 63) / 64, M / 128); }

extern "C" void kernel_launch(void* const* d_in, const int* in_sizes, int n_in,
                              void* d_out, int out_size)
{
    const float* image_features = (const float*)d_in[0];
    const float* text_features  = (const float*)d_in[1];
    const float* img_w    = (const float*)d_in[2];
    const float* img_b    = (const float*)d_in[3];
    const float* img_ln_g = (const float*)d_in[4];
    const float* img_ln_b = (const float*)d_in[5];
    const float* txt_w    = (const float*)d_in[6];
    const float* txt_b    = (const float*)d_in[7];
    const float* txt_ln_g = (const float*)d_in[8];
    const float* txt_ln_b = (const float*)d_in[9];
    const float* gate_w1  = (const float*)d_in[10];
    const float* gate_b1  = (const float*)d_in[11];
    const float* gate_w2  = (const float*)d_in[12];
    const float* gate_b2  = (const float*)d_in[13];
    const float* gate_w3  = (const float*)d_in[14];
    const float* gate_b3  = (const float*)d_in[15];
    const float* in_proj_w  = (const float*)d_in[16];
    const float* conv_w     = (const float*)d_in[17];
    const float* conv_b     = (const float*)d_in[18];
    const float* x_proj_w   = (const float*)d_in[19];
    const float* dt_proj_w  = (const float*)d_in[20];
    const float* dt_proj_b  = (const float*)d_in[21];
    /* d_in[22] = A_log: unused (L=1, h0=0 -> dA multiplies zero state) */
    const float* D_param    = (const float*)d_in[23];
    const float* out_proj_w = (const float*)d_in[24];
    const float* mnorm_g    = (const float*)d_in[25];
    const float* mnorm_b    = (const float*)d_in[26];
    const float* fc_w    = (const float*)d_in[27];
    const float* fc_b    = (const float*)d_in[28];
    const float* final_g = (const float*)d_in[29];
    const float* final_b = (const float*)d_in[30];

    float* out_fused = (float*)d_out;                       // [1024, 256]
    float* out_gate  = (float*)d_out + (size_t)BATCH * 256; // [1024, 2]

    float *cat, *x, *tA, *tB, *h1, *h2, *xz, *xc, *dbc, *delta, *u, *bcd, *mo, *fcb;
    cudaGetSymbolAddress((void**)&cat,   g_cat);
    cudaGetSymbolAddress((void**)&x,     g_x);
    cudaGetSymbolAddress((void**)&tA,    g_tmpA);
    cudaGetSymbolAddress((void**)&tB,    g_tmpB);
    cudaGetSymbolAddress((void**)&h1,    g_h1);
    cudaGetSymbolAddress((void**)&h2,    g_h2);
    cudaGetSymbolAddress((void**)&xz,    g_xz);
    cudaGetSymbolAddress((void**)&xc,    g_xc);
    cudaGetSymbolAddress((void**)&dbc,   g_dbc);
    cudaGetSymbolAddress((void**)&delta, g_delta);
    cudaGetSymbolAddress((void**)&u,     g_u);
    cudaGetSymbolAddress((void**)&bcd,   g_bcd);
    cudaGetSymbolAddress((void**)&mo,    g_mo);
    cudaGetSymbolAddress((void**)&fcb,   g_fc);

    // ---- align branches: 3x (gemm+relu -> LN); last LN writes into cat ----
    {
        const float* cur = image_features;
        for (int i = 0; i < 3; i++) {
            gemm_nt<EPI_RELU><<<ggrid(BATCH, DIMD), 256>>>(
                tA, cur, img_w + (size_t)i * DIMD * DIMD, img_b + (size_t)i * DIMD,
                BATCH, DIMD, DIMD, DIMD);
            float* lnout = (i == 2) ? cat : tB;
            ln_kernel<<<BATCH, 128>>>(lnout, tA, nullptr,
                                      img_ln_g + (size_t)i * DIMD, img_ln_b + (size_t)i * DIMD,
                                      DIMD, (i == 2) ? DM : DIMD);
            cur = tB;
        }
        cur = text_features;
        for (int i = 0; i < 3; i++) {
            gemm_nt<EPI_RELU><<<ggrid(BATCH, DIMD), 256>>>(
                tA, cur, txt_w + (size_t)i * DIMD * DIMD, txt_b + (size_t)i * DIMD,
                BATCH, DIMD, DIMD, DIMD);
            float* lnout = (i == 2) ? (cat + DIMD) : tB;
            ln_kernel<<<BATCH, 128>>>(lnout, tA, nullptr,
                                      txt_ln_g + (size_t)i * DIMD, txt_ln_b + (size_t)i * DIMD,
                                      DIMD, (i == 2) ? DM : DIMD);
            cur = tB;
        }
    }

    // ---- gate MLP -> softmax -> build x = [g0*img, g1*txt] ----
    gemm_nt<EPI_RELU><<<ggrid(BATCH, DIMD), 256>>>(h1, cat, gate_w1, gate_b1, BATCH, DIMD, DM, DM);
    gemm_nt<EPI_RELU><<<ggrid(BATCH, 256), 256>>>(h2, h1, gate_w2, gate_b2, BATCH, 256, DIMD, DIMD);
    gate_kernel<<<BATCH, 128>>>(x, out_gate, h2, cat, gate_w3, gate_b3);

    // ---- 3 mamba layers (L=1 collapsed) ----
    for (int l = 0; l < 3; l++) {
        gemm_nt<EPI_NONE><<<ggrid(BATCH, 2 * DI), 256>>>(
            xz, x, in_proj_w + (size_t)l * (2 * DI) * DM, nullptr, BATCH, 2 * DI, DM, DM);
        conv_silu_kernel<<<(BATCH * DI) / 256, 256>>>(
            xc, xz, conv_w + (size_t)l * DI * 4, conv_b + (size_t)l * DI);
        gemm_nt<EPI_NONE><<<ggrid(BATCH, 96), 256>>>(
            dbc, xc, x_proj_w + (size_t)l * 96 * DI, nullptr, BATCH, 96, DI, DI);
        bcdot_kernel<<<4, 256>>>(bcd, dbc);
        gemm_nt<EPI_SOFTPLUS><<<ggrid(BATCH, DI), 256>>>(
            delta, dbc, dt_proj_w + (size_t)l * DI * DTR, dt_proj_b + (size_t)l * DI,
            BATCH, DI, DTR, 96);
        ssm_kernel<<<(BATCH * DI) / 256, 256>>>(u, delta, xc, xz, bcd, D_param + (size_t)l * DI);
        gemm_nt<EPI_NONE><<<ggrid(BATCH, DM), 256>>>(
            mo, u, out_proj_w + (size_t)l * DM * DI, nullptr, BATCH, DM, DI, DI);
        ln_kernel<<<BATCH, 128>>>(x, mo, x, mnorm_g + (size_t)l * DM, mnorm_b + (size_t)l * DM,
                                  DM, DM);
    }

    // ---- final fc + LN -> fused output ----
    gemm_nt<EPI_BIAS><<<ggrid(BATCH, 256), 256>>>(fcb, x, fc_w, fc_b, BATCH, 256, DM, DM);
    ln_kernel<<<BATCH, 128>>>(out_fused, fcb, nullptr, final_g, final_b, 256, 256);
}

// round 8
// speedup vs baseline: 1.5375x; 1.5375x over previous
#include <cuda_runtime.h>
#include <cuda_bf16.h>
#include <cstdint>
#include <math.h>

#define BATCH 1024
#define DIMD  512
#define DM    1024
#define DI    2048
#define DTR   64
#define DS    16

// ---------------- static scratch (no allocations allowed) ----------------
__device__ float g_cat  [BATCH * DM];
__device__ float g_x    [BATCH * DM];
__device__ float g_tmpA [BATCH * DIMD];
__device__ float g_tmpB [BATCH * DIMD];
__device__ float g_h1   [BATCH * DIMD];
__device__ float g_h2   [BATCH * 256];
__device__ float g_xz   [BATCH * (2 * DI)];
__device__ float g_xc   [BATCH * DI];
__device__ float g_dbc  [BATCH * 96];
__device__ float g_delta[BATCH * DI];
__device__ float g_u    [BATCH * DI];
__device__ float g_bcd  [BATCH];
__device__ float g_mo   [BATCH * DM];
__device__ float g_fc   [BATCH * 256];

// ---------------- helpers ----------------
__device__ __forceinline__ float siluf(float x) { return x / (1.f + expf(-x)); }
__device__ __forceinline__ float softplusf_(float x) { return x > 20.f ? x : log1pf(expf(x)); }

enum { EPI_NONE = 0, EPI_RELU = 1, EPI_BIAS = 2, EPI_SOFTPLUS = 3 };

__device__ __forceinline__ uint32_t smem_to_u32(const void* p) {
    uint32_t a;
    asm("{ .reg .u64 tmp; cvta.to.shared.u64 tmp, %1; cvt.u32.u64 %0, tmp; }"
        : "=r"(a) : "l"(p));
    return a;
}
#define SMEM_SWIZZLE_128B(byte_offset) \
    ((byte_offset) ^ (((byte_offset) >> 3) & 0x70))

// mma.sync bf16 (baseline PTX, sm_80+; legal for compute_103 target)
__device__ __forceinline__ void mma_bf16(float* c, const uint32_t* a, const uint32_t* b) {
    asm volatile(
        "mma.sync.aligned.m16n8k16.row.col.f32.bf16.bf16.f32 "
        "{%0,%1,%2,%3}, {%4,%5,%6,%7}, {%8,%9}, {%0,%1,%2,%3};"
        : "+f"(c[0]), "+f"(c[1]), "+f"(c[2]), "+f"(c[3])
        : "r"(a[0]), "r"(a[1]), "r"(a[2]), "r"(a[3]), "r"(b[0]), "r"(b[1]));
}
__device__ __forceinline__ void ldsm4(uint32_t* r, uint32_t addr) {
    asm volatile("ldmatrix.sync.aligned.m8n8.x4.shared.b16 {%0,%1,%2,%3}, [%4];"
                 : "=r"(r[0]), "=r"(r[1]), "=r"(r[2]), "=r"(r[3]) : "r"(addr));
}
__device__ __forceinline__ void ldsm2(uint32_t* r, uint32_t addr) {
    asm volatile("ldmatrix.sync.aligned.m8n8.x2.shared.b16 {%0,%1}, [%2];"
                 : "=r"(r[0]), "=r"(r[1]) : "r"(addr));
}

// fp32x4 -> (4 bf16 hi, 4 bf16 lo) packed as uint2 each
__device__ __forceinline__ void split4(float4 v, uint2& hi, uint2& lo) {
    __nv_bfloat162 h01, h23;
    h01.x = __float2bfloat16(v.x); h01.y = __float2bfloat16(v.y);
    h23.x = __float2bfloat16(v.z); h23.y = __float2bfloat16(v.w);
    float l0 = v.x - __bfloat162float(h01.x);
    float l1 = v.y - __bfloat162float(h01.y);
    float l2 = v.z - __bfloat162float(h23.x);
    float l3 = v.w - __bfloat162float(h23.y);
    __nv_bfloat162 l01, l23;
    l01.x = __float2bfloat16(l0); l01.y = __float2bfloat16(l1);
    l23.x = __float2bfloat16(l2); l23.y = __float2bfloat16(l3);
    hi.x = *(uint32_t*)&h01; hi.y = *(uint32_t*)&h23;
    lo.x = *(uint32_t*)&l01; lo.y = *(uint32_t*)&l23;
}

// ================= tensor-core GEMM via mma.sync =========================
// C[M,N] = act(A[M,K] @ W[N,K]^T + bias)
// CTA tile 128x128, BK=32, 8 warps (warp tile 64x32), double-buffered.
// SMEM tile layout per operand: 128 rows x 128 bytes; row r holds
//   [0,64):  32 bf16 "hi" for k=0..31
//   [64,128):32 bf16 "lo" for k=0..31
// swizzled with SW128 -> conflict-free ldmatrix.
// buffers: A0 @0, B0 @16K, A1 @32K, B1 @48K (total 64KB dynamic smem)
static constexpr int MM_SMEM_BYTES = 65536;

template <int EPI>
__global__ void __launch_bounds__(256) gemm_mma(
    float* __restrict__ C, const float* __restrict__ A, const float* __restrict__ W,
    const float* __restrict__ bias, int M, int N, int K, int lda)
{
    extern __shared__ char smem[];
    const uint32_t sb = smem_to_u32(smem);
    const int tid = threadIdx.x;
    const int lane = tid & 31;
    const int wid = tid >> 5;
    const int wm = wid & 1;        // 0..1 -> m offset 0/64
    const int wn = wid >> 1;       // 0..3 -> n offset 0/32/64/96
    const int mBase = blockIdx.y * 128;
    const int nBase = blockIdx.x * 128;

    // ---- global load mapping: thread t covers row t>>1, k-half t&1 ----
    const int lrow = tid >> 1;
    const int lkh  = tid & 1;
    const float* gA = A + (size_t)(mBase + lrow) * lda + lkh * 16;
    const int brow = nBase + lrow;
    const float* gB = W + (size_t)brow * K + lkh * 16;
    const bool bvalid = brow < N;

    // precomputed STS offsets (logical, within one tile)
    uint32_t stsHi[4], stsLo[4];
#pragma unroll
    for (int i = 0; i < 4; i++) {
        uint32_t l = (uint32_t)lrow * 128u + (uint32_t)lkh * 32u + (uint32_t)i * 8u;
        stsHi[i] = SMEM_SWIZZLE_128B(l);
        stsLo[i] = SMEM_SWIZZLE_128B(l + 64u);
    }

    // ldmatrix address components
    const uint32_t a_row = (uint32_t)(wm * 64 + (lane & 15));
    const uint32_t a_cb  = ((uint32_t)(lane >> 4)) * 16u;     // k-chunk within 16k
    const uint32_t a_x   = (a_row & 7u) << 4;
    const uint32_t b_rl  = (uint32_t)(lane & 7);
    const uint32_t b_cb  = ((uint32_t)((lane >> 3) & 1)) * 16u;
    const uint32_t b_x   = b_rl << 4;

    float acc[4][4][4];
#pragma unroll
    for (int mf = 0; mf < 4; mf++)
#pragma unroll
        for (int nf = 0; nf < 4; nf++)
#pragma unroll
            for (int q = 0; q < 4; q++) acc[mf][nf][q] = 0.f;

    const int nch = K >> 5;   // K / 32
    float4 ra[4], rb[4];

    // ---- preload chunk 0 ----
#pragma unroll
    for (int i = 0; i < 4; i++) {
        ra[i] = *(const float4*)(gA + i * 4);
        rb[i] = bvalid ? *(const float4*)(gB + i * 4) : make_float4(0.f, 0.f, 0.f, 0.f);
    }
    {
        char* ab = smem;            // A buf0
        char* bb = smem + 16384;    // B buf0
#pragma unroll
        for (int i = 0; i < 4; i++) {
            uint2 h, l;
            split4(ra[i], h, l);
            *(uint2*)(ab + stsHi[i]) = h;
            *(uint2*)(ab + stsLo[i]) = l;
            split4(rb[i], h, l);
            *(uint2*)(bb + stsHi[i]) = h;
            *(uint2*)(bb + stsLo[i]) = l;
        }
    }
    __syncthreads();

    for (int ch = 0; ch < nch; ch++) {
        // prefetch next chunk to registers
        if (ch + 1 < nch) {
            const int k0 = (ch + 1) * 32;
#pragma unroll
            for (int i = 0; i < 4; i++) {
                ra[i] = *(const float4*)(gA + k0 + i * 4);
                rb[i] = bvalid ? *(const float4*)(gB + k0 + i * 4)
                               : make_float4(0.f, 0.f, 0.f, 0.f);
            }
        }

        // compute on buffer ch&1
        const uint32_t aAddr = sb + (uint32_t)(ch & 1) * 32768u;
        const uint32_t bAddr = aAddr + 16384u;
#pragma unroll
        for (int ks = 0; ks < 2; ks++) {
            uint32_t Ah[4][4], Al[4][4], Bh[4][2], Bl[4][2];
#pragma unroll
            for (int mf = 0; mf < 4; mf++) {
                uint32_t rbase = aAddr + (a_row + (uint32_t)mf * 16u) * 128u;
                ldsm4(Ah[mf], rbase + (((uint32_t)ks * 32u + a_cb) ^ a_x));
                ldsm4(Al[mf], rbase + ((64u + (uint32_t)ks * 32u + a_cb) ^ a_x));
            }
#pragma unroll
            for (int nf = 0; nf < 4; nf++) {
                uint32_t rbase = bAddr + ((uint32_t)(wn * 32 + nf * 8) + b_rl) * 128u;
                ldsm2(Bh[nf], rbase + (((uint32_t)ks * 32u + b_cb) ^ b_x));
                ldsm2(Bl[nf], rbase + ((64u + (uint32_t)ks * 32u + b_cb) ^ b_x));
            }
#pragma unroll
            for (int mf = 0; mf < 4; mf++)
#pragma unroll
                for (int nf = 0; nf < 4; nf++) {
                    mma_bf16(acc[mf][nf], Ah[mf], Bh[nf]);
                    mma_bf16(acc[mf][nf], Ah[mf], Bl[nf]);
                    mma_bf16(acc[mf][nf], Al[mf], Bh[nf]);
                }
        }

        // store next chunk into the other buffer
        if (ch + 1 < nch) {
            char* ab = smem + ((ch + 1) & 1) * 32768;
            char* bb = ab + 16384;
#pragma unroll
            for (int i = 0; i < 4; i++) {
                uint2 h, l;
                split4(ra[i], h, l);
                *(uint2*)(ab + stsHi[i]) = h;
                *(uint2*)(ab + stsLo[i]) = l;
                split4(rb[i], h, l);
                *(uint2*)(bb + stsHi[i]) = h;
                *(uint2*)(bb + stsLo[i]) = l;
            }
        }
        __syncthreads();
    }

    // ---- epilogue ----
    const int mrow0 = mBase + wm * 64 + (lane >> 2);
    const int ncol0 = nBase + wn * 32 + (lane & 3) * 2;
#pragma unroll
    for (int mf = 0; mf < 4; mf++) {
#pragma unroll
        for (int nf = 0; nf < 4; nf++) {
            const int col = ncol0 + nf * 8;
            if (col < N) {
                float bx = 0.f, by = 0.f;
                if (EPI != EPI_NONE) {
                    float2 bv = *(const float2*)(bias + col);
                    bx = bv.x; by = bv.y;
                }
                float v0 = acc[mf][nf][0] + bx, v1 = acc[mf][nf][1] + by;
                float v2 = acc[mf][nf][2] + bx, v3 = acc[mf][nf][3] + by;
                if (EPI == EPI_RELU) {
                    v0 = fmaxf(v0, 0.f); v1 = fmaxf(v1, 0.f);
                    v2 = fmaxf(v2, 0.f); v3 = fmaxf(v3, 0.f);
                }
                if (EPI == EPI_SOFTPLUS) {
                    v0 = softplusf_(v0); v1 = softplusf_(v1);
                    v2 = softplusf_(v2); v3 = softplusf_(v3);
                }
                const int r0 = mrow0 + mf * 16;
                float2 o0; o0.x = v0; o0.y = v1;
                float2 o1; o1.x = v2; o1.y = v3;
                *(float2*)(C + (size_t)r0 * N + col) = o0;
                *(float2*)(C + (size_t)(r0 + 8) * N + col) = o1;
            }
        }
    }
}

// ---------------- layernorm (optionally with residual add) ----------------
__global__ void __launch_bounds__(128) ln_kernel(
    float* __restrict__ out, const float* __restrict__ in, const float* __restrict__ res,
    const float* __restrict__ g, const float* __restrict__ b, int W, int out_stride)
{
    const int row = blockIdx.x;
    const int t = threadIdx.x;
    const int n = W >> 7;
    const float* ip = in + (size_t)row * W;
    const float* rp = res ? res + (size_t)row * W : nullptr;

    float v[8];
    float s = 0.f, q = 0.f;
    for (int i = 0; i < n; i++) {
        float val = ip[t + i * 128];
        if (rp) val += rp[t + i * 128];
        v[i] = val; s += val; q += val * val;
    }
    __shared__ float ss[4], qs[4];
    for (int o = 16; o > 0; o >>= 1) {
        s += __shfl_down_sync(0xffffffffu, s, o);
        q += __shfl_down_sync(0xffffffffu, q, o);
    }
    if ((t & 31) == 0) { ss[t >> 5] = s; qs[t >> 5] = q; }
    __syncthreads();
    __shared__ float mean_s, rstd_s;
    if (t == 0) {
        float S = ss[0] + ss[1] + ss[2] + ss[3];
        float Q = qs[0] + qs[1] + qs[2] + qs[3];
        float m = S / (float)W;
        float var = Q / (float)W - m * m;
        mean_s = m;
        rstd_s = rsqrtf(var + 1e-5f);
    }
    __syncthreads();
    const float m = mean_s, r = rstd_s;
    float* op = out + (size_t)row * out_stride;
    for (int i = 0; i < n; i++) {
        int idx = t + i * 128;
        op[idx] = (v[i] - m) * r * g[idx] + b[idx];
    }
}

// ---------------- gate head ----------------
__global__ void __launch_bounds__(128) gate_kernel(
    float* __restrict__ x, float* __restrict__ gate_out, const float* __restrict__ h2,
    const float* __restrict__ cat, const float* __restrict__ w3, const float* __restrict__ b3)
{
    const int bi = blockIdx.x;
    const int t = threadIdx.x;
    const float* h = h2 + (size_t)bi * 256;
    float p0 = 0.f, p1 = 0.f;
    for (int i = t; i < 256; i += 128) {
        float hv = h[i];
        p0 += hv * w3[i];
        p1 += hv * w3[256 + i];
    }
    __shared__ float s0[4], s1[4];
    for (int o = 16; o > 0; o >>= 1) {
        p0 += __shfl_down_sync(0xffffffffu, p0, o);
        p1 += __shfl_down_sync(0xffffffffu, p1, o);
    }
    if ((t & 31) == 0) { s0[t >> 5] = p0; s1[t >> 5] = p1; }
    __syncthreads();
    __shared__ float g0s, g1s;
    if (t == 0) {
        float l0 = s0[0] + s0[1] + s0[2] + s0[3] + b3[0];
        float l1 = s1[0] + s1[1] + s1[2] + s1[3] + b3[1];
        float mx = fmaxf(l0, l1);
        float e0 = expf(l0 - mx), e1 = expf(l1 - mx);
        float inv = 1.f / (e0 + e1);
        g0s = e0 * inv; g1s = e1 * inv;
        gate_out[bi * 2 + 0] = g0s;
        gate_out[bi * 2 + 1] = g1s;
    }
    __syncthreads();
    const float g0 = g0s, g1 = g1s;
    const float* c = cat + (size_t)bi * DM;
    float* xo = x + (size_t)bi * DM;
    for (int i = t; i < DM; i += 128) xo[i] = c[i] * (i < DIMD ? g0 : g1);
}

// ---------------- conv (L=1 -> single tap) + silu ----------------
__global__ void __launch_bounds__(256) conv_silu_kernel(
    float* __restrict__ xc, const float* __restrict__ xz,
    const float* __restrict__ cw, const float* __restrict__ cb)
{
    int idx = blockIdx.x * 256 + threadIdx.x;
    int d = idx & (DI - 1);
    int bi = idx >> 11;
    float v = xz[(size_t)bi * (2 * DI) + d] * cw[d * 4 + 3] + cb[d];
    xc[idx] = siluf(v);
}

// ---------------- per-batch Bc . Cc ----------------
__global__ void bcdot_kernel(float* __restrict__ bcd, const float* __restrict__ dbc)
{
    int bi = blockIdx.x * blockDim.x + threadIdx.x;
    if (bi < BATCH) {
        const float* p = dbc + (size_t)bi * 96;
        float s = 0.f;
#pragma unroll
        for (int i = 0; i < DS; i++) s += p[64 + i] * p[80 + i];
        bcd[bi] = s;
    }
}

// ---------------- ssm collapse (L=1) + silu(z) gating ----------------
__global__ void __launch_bounds__(256) ssm_kernel(
    float* __restrict__ u, const float* __restrict__ delta, const float* __restrict__ xc,
    const float* __restrict__ xz, const float* __restrict__ bcd, const float* __restrict__ Dp)
{
    int idx = blockIdx.x * 256 + threadIdx.x;
    int d = idx & (DI - 1);
    int bi = idx >> 11;
    float z = xz[(size_t)bi * (2 * DI) + DI + d];
    float y = xc[idx] * (delta[idx] * bcd[bi] + Dp[d]);
    u[idx] = y * siluf(z);
}

// ---------------- launch ----------------
static inline dim3 tgrid(int M, int N) { return dim3((N + 127) / 128, M / 128); }

extern "C" void kernel_launch(void* const* d_in, const int* in_sizes, int n_in,
                              void* d_out, int out_size)
{
    const float* image_features = (const float*)d_in[0];
    const float* text_features  = (const float*)d_in[1];
    const float* img_w    = (const float*)d_in[2];
    const float* img_b    = (const float*)d_in[3];
    const float* img_ln_g = (const float*)d_in[4];
    const float* img_ln_b = (const float*)d_in[5];
    const float* txt_w    = (const float*)d_in[6];
    const float* txt_b    = (const float*)d_in[7];
    const float* txt_ln_g = (const float*)d_in[8];
    const float* txt_ln_b = (const float*)d_in[9];
    const float* gate_w1  = (const float*)d_in[10];
    const float* gate_b1  = (const float*)d_in[11];
    const float* gate_w2  = (const float*)d_in[12];
    const float* gate_b2  = (const float*)d_in[13];
    const float* gate_w3  = (const float*)d_in[14];
    const float* gate_b3  = (const float*)d_in[15];
    const float* in_proj_w  = (const float*)d_in[16];
    const float* conv_w     = (const float*)d_in[17];
    const float* conv_b     = (const float*)d_in[18];
    const float* x_proj_w   = (const float*)d_in[19];
    const float* dt_proj_w  = (const float*)d_in[20];
    const float* dt_proj_b  = (const float*)d_in[21];
    /* d_in[22] = A_log: unused (L=1, h0=0) */
    const float* D_param    = (const float*)d_in[23];
    const float* out_proj_w = (const float*)d_in[24];
    const float* mnorm_g    = (const float*)d_in[25];
    const float* mnorm_b    = (const float*)d_in[26];
    const float* fc_w    = (const float*)d_in[27];
    const float* fc_b    = (const float*)d_in[28];
    const float* final_g = (const float*)d_in[29];
    const float* final_b = (const float*)d_in[30];

    float* out_fused = (float*)d_out;
    float* out_gate  = (float*)d_out + (size_t)BATCH * 256;

    float *cat, *x, *tA, *tB, *h1, *h2, *xz, *xc, *dbc, *delta, *u, *bcd, *mo, *fcb;
    cudaGetSymbolAddress((void**)&cat,   g_cat);
    cudaGetSymbolAddress((void**)&x,     g_x);
    cudaGetSymbolAddress((void**)&tA,    g_tmpA);
    cudaGetSymbolAddress((void**)&tB,    g_tmpB);
    cudaGetSymbolAddress((void**)&h1,    g_h1);
    cudaGetSymbolAddress((void**)&h2,    g_h2);
    cudaGetSymbolAddress((void**)&xz,    g_xz);
    cudaGetSymbolAddress((void**)&xc,    g_xc);
    cudaGetSymbolAddress((void**)&dbc,   g_dbc);
    cudaGetSymbolAddress((void**)&delta, g_delta);
    cudaGetSymbolAddress((void**)&u,     g_u);
    cudaGetSymbolAddress((void**)&bcd,   g_bcd);
    cudaGetSymbolAddress((void**)&mo,    g_mo);
    cudaGetSymbolAddress((void**)&fcb,   g_fc);

    // allow 64KB dynamic smem (host-side attr; legal during graph capture)
    cudaFuncSetAttribute(gemm_mma<EPI_NONE>,
                         cudaFuncAttributeMaxDynamicSharedMemorySize, MM_SMEM_BYTES);
    cudaFuncSetAttribute(gemm_mma<EPI_RELU>,
                         cudaFuncAttributeMaxDynamicSharedMemorySize, MM_SMEM_BYTES);
    cudaFuncSetAttribute(gemm_mma<EPI_BIAS>,
                         cudaFuncAttributeMaxDynamicSharedMemorySize, MM_SMEM_BYTES);
    cudaFuncSetAttribute(gemm_mma<EPI_SOFTPLUS>,
                         cudaFuncAttributeMaxDynamicSharedMemorySize, MM_SMEM_BYTES);

    // ---- align branches: 3x (gemm+relu -> LN); last LN writes into cat ----
    {
        const float* cur = image_features;
        for (int i = 0; i < 3; i++) {
            gemm_mma<EPI_RELU><<<tgrid(BATCH, DIMD), 256, MM_SMEM_BYTES>>>(
                tA, cur, img_w + (size_t)i * DIMD * DIMD, img_b + (size_t)i * DIMD,
                BATCH, DIMD, DIMD, DIMD);
            float* lnout = (i == 2) ? cat : tB;
            ln_kernel<<<BATCH, 128>>>(lnout, tA, nullptr,
                                      img_ln_g + (size_t)i * DIMD, img_ln_b + (size_t)i * DIMD,
                                      DIMD, (i == 2) ? DM : DIMD);
            cur = tB;
        }
        cur = text_features;
        for (int i = 0; i < 3; i++) {
            gemm_mma<EPI_RELU><<<tgrid(BATCH, DIMD), 256, MM_SMEM_BYTES>>>(
                tA, cur, txt_w + (size_t)i * DIMD * DIMD, txt_b + (size_t)i * DIMD,
                BATCH, DIMD, DIMD, DIMD);
            float* lnout = (i == 2) ? (cat + DIMD) : tB;
            ln_kernel<<<BATCH, 128>>>(lnout, tA, nullptr,
                                      txt_ln_g + (size_t)i * DIMD, txt_ln_b + (size_t)i * DIMD,
                                      DIMD, (i == 2) ? DM : DIMD);
            cur = tB;
        }
    }

    // ---- gate MLP -> softmax -> build x ----
    gemm_mma<EPI_RELU><<<tgrid(BATCH, DIMD), 256, MM_SMEM_BYTES>>>(
        h1, cat, gate_w1, gate_b1, BATCH, DIMD, DM, DM);
    gemm_mma<EPI_RELU><<<tgrid(BATCH, 256), 256, MM_SMEM_BYTES>>>(
        h2, h1, gate_w2, gate_b2, BATCH, 256, DIMD, DIMD);
    gate_kernel<<<BATCH, 128>>>(x, out_gate, h2, cat, gate_w3, gate_b3);

    // ---- 3 mamba layers (L=1 collapsed) ----
    for (int l = 0; l < 3; l++) {
        gemm_mma<EPI_NONE><<<tgrid(BATCH, 2 * DI), 256, MM_SMEM_BYTES>>>(
            xz, x, in_proj_w + (size_t)l * (2 * DI) * DM, nullptr, BATCH, 2 * DI, DM, DM);
        conv_silu_kernel<<<(BATCH * DI) / 256, 256>>>(
            xc, xz, conv_w + (size_t)l * DI * 4, conv_b + (size_t)l * DI);
        gemm_mma<EPI_NONE><<<tgrid(BATCH, 96), 256, MM_SMEM_BYTES>>>(
            dbc, xc, x_proj_w + (size_t)l * 96 * DI, nullptr, BATCH, 96, DI, DI);
        bcdot_kernel<<<4, 256>>>(bcd, dbc);
        gemm_mma<EPI_SOFTPLUS><<<tgrid(BATCH, DI), 256, MM_SMEM_BYTES>>>(
            delta, dbc, dt_proj_w + (size_t)l * DI * DTR, dt_proj_b + (size_t)l * DI,
            BATCH, DI, DTR, 96);
        ssm_kernel<<<(BATCH * DI) / 256, 256>>>(u, delta, xc, xz, bcd, D_param + (size_t)l * DI);
        gemm_mma<EPI_NONE><<<tgrid(BATCH, DM), 256, MM_SMEM_BYTES>>>(
            mo, u, out_proj_w + (size_t)l * DM * DI, nullptr, BATCH, DM, DI, DI);
        ln_kernel<<<BATCH, 128>>>(x, mo, x, mnorm_g + (size_t)l * DM, mnorm_b + (size_t)l * DM,
                                  DM, DM);
    }

    // ---- final fc + LN -> fused output ----
    gemm_mma<EPI_BIAS><<<tgrid(BATCH, 256), 256, MM_SMEM_BYTES>>>(
        fcb, x, fc_w, fc_b, BATCH, 256, DM, DM);
    ln_kernel<<<BATCH, 128>>>(out_fused, fcb, nullptr, final_g, final_b, 256, 256);
}

// round 10
// speedup vs baseline: 2.8396x; 1.8469x over previous
#include <cuda_runtime.h>
#include <cuda_fp16.h>
#include <cstdint>
#include <math.h>

#define BATCH 1024
#define DIMD  512
#define DM    1024
#define DI    2048
#define DTR   64
#define DS    16

// ---------------- static fp32 scratch ----------------
__device__ float g_cat [BATCH * DM];
__device__ float g_x   [BATCH * DM];
__device__ float g_tA2 [2 * BATCH * DIMD];   // batched align gemm out (img+txt)
__device__ float g_h2  [BATCH * 256];
__device__ float g_xz  [BATCH * (2 * DI)];
__device__ float g_xc  [BATCH * DI];
__device__ float g_dbc [BATCH * 96];
__device__ float g_bcd [BATCH];
__device__ float g_mo  [BATCH * DM];
__device__ float g_fc  [BATCH * 256];

// ---------------- static fp16 scratch ----------------
__device__ __half h_wimg[3 * DIMD * DIMD];
__device__ __half h_wtxt[3 * DIMD * DIMD];
__device__ __half h_wg1 [DIMD * DM];
__device__ __half h_wg2 [256 * DIMD];
__device__ __half h_winp[3 * (2 * DI) * DM];
__device__ __half h_wxp [3 * 96 * DI];
__device__ __half h_wdt [3 * DI * DTR];
__device__ __half h_wop [3 * DM * DI];
__device__ __half h_wfc [256 * DM];
__device__ __half h_feat[2 * BATCH * DIMD];
__device__ __half h_tB2 [2 * BATCH * DIMD];
__device__ __half h_cat [BATCH * DM];
__device__ __half h_h1  [BATCH * DIMD];
__device__ __half h_x   [BATCH * DM];
__device__ __half h_xc  [BATCH * DI];
__device__ __half h_dbc [BATCH * 96];
__device__ __half h_u   [BATCH * DI];

// ---------------- helpers ----------------
__device__ __forceinline__ float siluf(float x) { return x / (1.f + expf(-x)); }
__device__ __forceinline__ float softplusf_(float x) { return x > 20.f ? x : log1pf(expf(x)); }

enum { EPI_NONE = 0, EPI_RELU = 1, EPI_BIAS = 2, EPI_INPROJ = 4, EPI_SSM = 5 };

__device__ __forceinline__ uint32_t smem_to_u32(const void* p) {
    uint32_t a;
    asm("{ .reg .u64 tmp; cvta.to.shared.u64 tmp, %1; cvt.u32.u64 %0, tmp; }"
        : "=r"(a) : "l"(p));
    return a;
}
#define SMEM_SWIZZLE_128B(byte_offset) \
    ((byte_offset) ^ (((byte_offset) >> 3) & 0x70))

__device__ __forceinline__ void mma_f16(float* c, const uint32_t* a, const uint32_t* b) {
    asm volatile(
        "mma.sync.aligned.m16n8k16.row.col.f32.f16.f16.f32 "
        "{%0,%1,%2,%3}, {%4,%5,%6,%7}, {%8,%9}, {%0,%1,%2,%3};"
        : "+f"(c[0]), "+f"(c[1]), "+f"(c[2]), "+f"(c[3])
        : "r"(a[0]), "r"(a[1]), "r"(a[2]), "r"(a[3]), "r"(b[0]), "r"(b[1]));
}
__device__ __forceinline__ void ldsm4(uint32_t* r, uint32_t addr) {
    asm volatile("ldmatrix.sync.aligned.m8n8.x4.shared.b16 {%0,%1,%2,%3}, [%4];"
                 : "=r"(r[0]), "=r"(r[1]), "=r"(r[2]), "=r"(r[3]) : "r"(addr));
}
__device__ __forceinline__ void ldsm2(uint32_t* r, uint32_t addr) {
    asm volatile("ldmatrix.sync.aligned.m8n8.x2.shared.b16 {%0,%1}, [%2];"
                 : "=r"(r[0]), "=r"(r[1]) : "r"(addr));
}
__device__ __forceinline__ void cp_async16(uint32_t dst, const void* src, uint32_t sz) {
    asm volatile("cp.async.ca.shared.global [%0], [%1], 16, %2;"
                 :: "r"(dst), "l"(src), "r"(sz));
}

// ================= fp32 -> fp16 batch conversion =========================
#define NSEG 11
struct ConvArgs {
    const float4* src[NSEG];
    __half* dst[NSEG];
    int off[NSEG + 1];   // cumulative, in float4 units
};
__global__ void __launch_bounds__(256) conv_half_kernel(ConvArgs a, int total4)
{
    for (int idx = blockIdx.x * 256 + threadIdx.x; idx < total4;
         idx += gridDim.x * 256) {
        int seg = 0;
#pragma unroll
        for (int s = 1; s < NSEG; s++) if (idx >= a.off[s]) seg = s;
        int j = idx - a.off[seg];
        float4 v = a.src[seg][j];
        __half2* d = (__half2*)(a.dst[seg] + (size_t)j * 4);
        d[0] = __floats2half2_rn(v.x, v.y);
        d[1] = __floats2half2_rn(v.z, v.w);
    }
}

// ================= fp16 tensor-core GEMM =================================
// C = act(A[M,K] @ W[N,K]^T + bias)   (A, W already fp16)
// CTA 128x128, BK=64, 8 warps (warp tile 64x32), double-buffered cp.async.
// SMEM: stage s at s*32KB; A tile at +0 (128 rows x 128B), B at +16KB.
static constexpr int MM_SMEM_BYTES = 65536;

template <int EPI>
__global__ void __launch_bounds__(256) gemm_mma(
    const __half* __restrict__ A, const __half* __restrict__ Wm,
    const __half* __restrict__ Wm2, int Msplit,
    int M, int N, int K, int lda,
    float* __restrict__ C, __half* __restrict__ C16,
    const float* __restrict__ bias, const float* __restrict__ bias2,
    float* __restrict__ X, __half* __restrict__ X16,
    const float* __restrict__ p0, const float* __restrict__ p1,
    const float* __restrict__ p2, const float* __restrict__ p3)
{
    extern __shared__ char smem[];
    const uint32_t sb = smem_to_u32(smem);
    const int tid = threadIdx.x;
    const int lane = tid & 31;
    const int wid = tid >> 5;
    const int wm = wid & 1;
    const int wn = wid >> 1;
    const int mBase = blockIdx.y * 128;
    const int nBase = blockIdx.x * 128;

    const __half* Wsel = (mBase >= Msplit) ? Wm2 : Wm;
    const float* bsel  = (mBase >= Msplit) ? bias2 : bias;

    // ---- loader: threads 0-127 -> A rows, 128-255 -> B rows ----
    const int op = tid >> 7;
    const int lrow = tid & 127;
    const __half* gsrc;
    uint32_t srcsz = 16;
    if (op == 0) {
        gsrc = A + (size_t)(mBase + lrow) * lda;
    } else {
        int grow = nBase + lrow;
        gsrc = Wsel + (size_t)(grow < N ? grow : 0) * K;
        if (grow >= N) srcsz = 0;
    }
    uint32_t dsw[8];
#pragma unroll
    for (int j = 0; j < 8; j++)
        dsw[j] = (uint32_t)(op * 16384) +
                 SMEM_SWIZZLE_128B((uint32_t)lrow * 128u + (uint32_t)j * 16u);

    // ldmatrix address components
    const uint32_t a_row = (uint32_t)(wm * 64 + (lane & 15));
    const uint32_t a_cb  = ((uint32_t)(lane >> 4)) * 16u;
    const uint32_t a_x   = (a_row & 7u) << 4;
    const uint32_t b_rl  = (uint32_t)(lane & 7);
    const uint32_t b_cb  = ((uint32_t)((lane >> 3) & 1)) * 16u;
    const uint32_t b_x   = b_rl << 4;

    float acc[4][4][4];
#pragma unroll
    for (int mf = 0; mf < 4; mf++)
#pragma unroll
        for (int nf = 0; nf < 4; nf++)
#pragma unroll
            for (int q = 0; q < 4; q++) acc[mf][nf][q] = 0.f;

    const int nch = K >> 6;

    // issue chunk 0 -> stage 0
#pragma unroll
    for (int j = 0; j < 8; j++) cp_async16(sb + dsw[j], gsrc + j * 8, srcsz);
    asm volatile("cp.async.commit_group;");

    for (int ch = 0; ch < nch; ch++) {
        if (ch + 1 < nch) {
            const __half* s = gsrc + (ch + 1) * 64;
            uint32_t base = sb + (uint32_t)((ch + 1) & 1) * 32768u;
#pragma unroll
            for (int j = 0; j < 8; j++) cp_async16(base + dsw[j], s + j * 8, srcsz);
            asm volatile("cp.async.commit_group;");
            asm volatile("cp.async.wait_group 1;");
        } else {
            asm volatile("cp.async.wait_group 0;");
        }
        __syncthreads();

        const uint32_t aAddr = sb + (uint32_t)(ch & 1) * 32768u;
        const uint32_t bAddr = aAddr + 16384u;
#pragma unroll
        for (int ks = 0; ks < 4; ks++) {
            uint32_t Af[4][4], Bf[4][2];
#pragma unroll
            for (int mf = 0; mf < 4; mf++)
                ldsm4(Af[mf], aAddr + (a_row + (uint32_t)mf * 16u) * 128u +
                              (((uint32_t)ks * 32u + a_cb) ^ a_x));
#pragma unroll
            for (int nf = 0; nf < 4; nf++)
                ldsm2(Bf[nf], bAddr + ((uint32_t)(wn * 32 + nf * 8) + b_rl) * 128u +
                              (((uint32_t)ks * 32u + b_cb) ^ b_x));
#pragma unroll
            for (int mf = 0; mf < 4; mf++)
#pragma unroll
                for (int nf = 0; nf < 4; nf++)
                    mma_f16(acc[mf][nf], Af[mf], Bf[nf]);
        }
        __syncthreads();
    }

    // ---- epilogue ----
    const int mrow0 = mBase + wm * 64 + (lane >> 2);
    const int ncol0 = nBase + wn * 32 + (lane & 3) * 2;
#pragma unroll
    for (int mf = 0; mf < 4; mf++) {
        const int r0 = mrow0 + mf * 16;
        const int r1 = r0 + 8;
#pragma unroll
        for (int nf = 0; nf < 4; nf++) {
            const int col = ncol0 + nf * 8;
            if (col >= N) continue;
            float v0 = acc[mf][nf][0], v1 = acc[mf][nf][1];
            float v2 = acc[mf][nf][2], v3 = acc[mf][nf][3];

            if (EPI == EPI_INPROJ) {
                float2 o0; o0.x = v0; o0.y = v1;
                float2 o1; o1.x = v2; o1.y = v3;
                *(float2*)(C + (size_t)r0 * N + col) = o0;
                *(float2*)(C + (size_t)r1 * N + col) = o1;
                if (col < DI) {
                    float w0 = p0[col * 4 + 3], w1 = p0[(col + 1) * 4 + 3];
                    float cb0 = p1[col], cb1 = p1[col + 1];
                    float x0 = siluf(v0 * w0 + cb0), x1 = siluf(v1 * w1 + cb1);
                    float x2 = siluf(v2 * w0 + cb0), x3 = siluf(v3 * w1 + cb1);
                    float2 a0; a0.x = x0; a0.y = x1;
                    float2 a1; a1.x = x2; a1.y = x3;
                    *(float2*)(X + (size_t)r0 * DI + col) = a0;
                    *(float2*)(X + (size_t)r1 * DI + col) = a1;
                    *(__half2*)(X16 + (size_t)r0 * DI + col) = __floats2half2_rn(x0, x1);
                    *(__half2*)(X16 + (size_t)r1 * DI + col) = __floats2half2_rn(x2, x3);
                }
            } else if (EPI == EPI_SSM) {
                float bb0 = bsel[col], bb1 = bsel[col + 1];
                float d0 = softplusf_(v0 + bb0), d1 = softplusf_(v1 + bb1);
                float d2 = softplusf_(v2 + bb0), d3 = softplusf_(v3 + bb1);
                float D0 = p3[col], D1 = p3[col + 1];
                float bc0 = p2[r0], bc1 = p2[r1];
                float2 xcA = *(const float2*)(p0 + (size_t)r0 * DI + col);
                float2 xcB = *(const float2*)(p0 + (size_t)r1 * DI + col);
                float2 zA = *(const float2*)(p1 + (size_t)r0 * (2 * DI) + DI + col);
                float2 zB = *(const float2*)(p1 + (size_t)r1 * (2 * DI) + DI + col);
                float u0 = xcA.x * (d0 * bc0 + D0) * siluf(zA.x);
                float u1 = xcA.y * (d1 * bc0 + D1) * siluf(zA.y);
                float u2 = xcB.x * (d2 * bc1 + D0) * siluf(zB.x);
                float u3 = xcB.y * (d3 * bc1 + D1) * siluf(zB.y);
                *(__half2*)(C16 + (size_t)r0 * N + col) = __floats2half2_rn(u0, u1);
                *(__half2*)(C16 + (size_t)r1 * N + col) = __floats2half2_rn(u2, u3);
            } else {
                if (EPI == EPI_RELU || EPI == EPI_BIAS) {
                    float bx = bsel[col], by = bsel[col + 1];
                    v0 += bx; v1 += by; v2 += bx; v3 += by;
                }
                if (EPI == EPI_RELU) {
                    v0 = fmaxf(v0, 0.f); v1 = fmaxf(v1, 0.f);
                    v2 = fmaxf(v2, 0.f); v3 = fmaxf(v3, 0.f);
                }
                if (C) {
                    float2 o0; o0.x = v0; o0.y = v1;
                    float2 o1; o1.x = v2; o1.y = v3;
                    *(float2*)(C + (size_t)r0 * N + col) = o0;
                    *(float2*)(C + (size_t)r1 * N + col) = o1;
                }
                if (C16) {
                    *(__half2*)(C16 + (size_t)r0 * N + col) = __floats2half2_rn(v0, v1);
                    *(__half2*)(C16 + (size_t)r1 * N + col) = __floats2half2_rn(v2, v3);
                }
            }
        }
    }
}

// ================= warp-per-row layernorm ================================
__global__ void __launch_bounds__(256) ln_warp(
    float* __restrict__ out, __half* __restrict__ out16,
    const float* __restrict__ in, const float* __restrict__ res,
    const float* __restrict__ g, const float* __restrict__ b,
    int W, int ostride, int o16stride, int rows)
{
    const int gw = (blockIdx.x * blockDim.x + threadIdx.x) >> 5;
    const int lane = threadIdx.x & 31;
    if (gw >= rows) return;
    const float4* ip = (const float4*)(in + (size_t)gw * W);
    const float4* rp = res ? (const float4*)(res + (size_t)gw * W) : nullptr;
    const int nv = W >> 7;
    float4 v[8];
    float s = 0.f, q = 0.f;
#pragma unroll 8
    for (int i = 0; i < nv; i++) {
        float4 t = ip[lane + i * 32];
        if (rp) {
            float4 r2 = rp[lane + i * 32];
            t.x += r2.x; t.y += r2.y; t.z += r2.z; t.w += r2.w;
        }
        v[i] = t;
        s += t.x + t.y + t.z + t.w;
        q += t.x * t.x + t.y * t.y + t.z * t.z + t.w * t.w;
    }
#pragma unroll
    for (int o = 16; o > 0; o >>= 1) {
        s += __shfl_xor_sync(0xffffffffu, s, o);
        q += __shfl_xor_sync(0xffffffffu, q, o);
    }
    const float m = s / (float)W;
    const float r = rsqrtf(q / (float)W - m * m + 1e-5f);
#pragma unroll 8
    for (int i = 0; i < nv; i++) {
        const int i4 = lane + i * 32;
        float4 gg = ((const float4*)g)[i4];
        float4 bb = ((const float4*)b)[i4];
        float4 o;
        o.x = (v[i].x - m) * r * gg.x + bb.x;
        o.y = (v[i].y - m) * r * gg.y + bb.y;
        o.z = (v[i].z - m) * r * gg.z + bb.z;
        o.w = (v[i].w - m) * r * gg.w + bb.w;
        if (out) ((float4*)(out + (size_t)gw * ostride))[i4] = o;
        if (out16) {
            __half2* hp = (__half2*)(out16 + (size_t)gw * o16stride + i4 * 4);
            hp[0] = __floats2half2_rn(o.x, o.y);
            hp[1] = __floats2half2_rn(o.z, o.w);
        }
    }
}

// batched align LN: rows 0-1023 = img set, 1024-2047 = txt set (W=512)
__global__ void __launch_bounds__(256) ln_warp2(
    const float* __restrict__ in,
    float* __restrict__ out0, float* __restrict__ out1,
    __half* __restrict__ o16a, __half* __restrict__ o16b,
    const float* __restrict__ g0, const float* __restrict__ b0,
    const float* __restrict__ g1, const float* __restrict__ b1,
    int ostride, int o16stride)
{
    const int gw = (blockIdx.x * blockDim.x + threadIdx.x) >> 5;
    const int lane = threadIdx.x & 31;
    if (gw >= 2048) return;
    const int set = gw >> 10;
    const int rr = gw & 1023;
    const float* g = set ? g1 : g0;
    const float* b = set ? b1 : b0;
    float* out = set ? out1 : out0;
    __half* o16 = set ? o16b : o16a;
    const float4* ip = (const float4*)(in + (size_t)gw * 512);
    float4 v[4];
    float s = 0.f, q = 0.f;
#pragma unroll
    for (int i = 0; i < 4; i++) {
        float4 t = ip[lane + i * 32];
        v[i] = t;
        s += t.x + t.y + t.z + t.w;
        q += t.x * t.x + t.y * t.y + t.z * t.z + t.w * t.w;
    }
#pragma unroll
    for (int o = 16; o > 0; o >>= 1) {
        s += __shfl_xor_sync(0xffffffffu, s, o);
        q += __shfl_xor_sync(0xffffffffu, q, o);
    }
    const float m = s / 512.f;
    const float r = rsqrtf(q / 512.f - m * m + 1e-5f);
#pragma unroll
    for (int i = 0; i < 4; i++) {
        const int i4 = lane + i * 32;
        float4 gg = ((const float4*)g)[i4];
        float4 bb = ((const float4*)b)[i4];
        float4 o;
        o.x = (v[i].x - m) * r * gg.x + bb.x;
        o.y = (v[i].y - m) * r * gg.y + bb.y;
        o.z = (v[i].z - m) * r * gg.z + bb.z;
        o.w = (v[i].w - m) * r * gg.w + bb.w;
        if (out) ((float4*)(out + (size_t)rr * ostride))[i4] = o;
        if (o16) {
            __half2* hp = (__half2*)(o16 + (size_t)rr * o16stride + i4 * 4);
            hp[0] = __floats2half2_rn(o.x, o.y);
            hp[1] = __floats2half2_rn(o.z, o.w);
        }
    }
}

// ---------------- gate head ----------------
__global__ void __launch_bounds__(128) gate_kernel(
    float* __restrict__ x, __half* __restrict__ x16,
    float* __restrict__ gate_out, const float* __restrict__ h2,
    const float* __restrict__ cat, const float* __restrict__ w3,
    const float* __restrict__ b3)
{
    const int bi = blockIdx.x;
    const int t = threadIdx.x;
    const float* h = h2 + (size_t)bi * 256;
    float p0 = 0.f, p1 = 0.f;
    for (int i = t; i < 256; i += 128) {
        float hv = h[i];
        p0 += hv * w3[i];
        p1 += hv * w3[256 + i];
    }
    __shared__ float s0[4], s1[4];
    for (int o = 16; o > 0; o >>= 1) {
        p0 += __shfl_down_sync(0xffffffffu, p0, o);
        p1 += __shfl_down_sync(0xffffffffu, p1, o);
    }
    if ((t & 31) == 0) { s0[t >> 5] = p0; s1[t >> 5] = p1; }
    __syncthreads();
    __shared__ float g0s, g1s;
    if (t == 0) {
        float l0 = s0[0] + s0[1] + s0[2] + s0[3] + b3[0];
        float l1 = s1[0] + s1[1] + s1[2] + s1[3] + b3[1];
        float mx = fmaxf(l0, l1);
        float e0 = expf(l0 - mx), e1 = expf(l1 - mx);
        float inv = 1.f / (e0 + e1);
        g0s = e0 * inv; g1s = e1 * inv;
        gate_out[bi * 2 + 0] = g0s;
        gate_out[bi * 2 + 1] = g1s;
    }
    __syncthreads();
    const float g0 = g0s, g1 = g1s;
    const float* c = cat + (size_t)bi * DM;
    float* xo = x + (size_t)bi * DM;
    __half* xo16 = x16 + (size_t)bi * DM;
    for (int i = t; i < DM; i += 128) {
        float val = c[i] * (i < DIMD ? g0 : g1);
        xo[i] = val;
        xo16[i] = __float2half(val);
    }
}

// ---------------- per-batch Bc . Cc ----------------
__global__ void bcdot_kernel(float* __restrict__ bcd, const float* __restrict__ dbc)
{
    int bi = blockIdx.x * blockDim.x + threadIdx.x;
    if (bi < BATCH) {
        const float* p = dbc + (size_t)bi * 96;
        float s = 0.f;
#pragma unroll
        for (int i = 0; i < DS; i++) s += p[64 + i] * p[80 + i];
        bcd[bi] = s;
    }
}

// ---------------- launch ----------------
static inline dim3 tgrid(int M, int N) { return dim3((N + 127) / 128, M / 128); }
static constexpr int MBIG = 1 << 30;

extern "C" void kernel_launch(void* const* d_in, const int* in_sizes, int n_in,
                              void* d_out, int out_size)
{
    const float* image_features = (const float*)d_in[0];
    const float* text_features  = (const float*)d_in[1];
    const float* img_w    = (const float*)d_in[2];
    const float* img_b    = (const float*)d_in[3];
    const float* img_ln_g = (const float*)d_in[4];
    const float* img_ln_b = (const float*)d_in[5];
    const float* txt_w    = (const float*)d_in[6];
    const float* txt_b    = (const float*)d_in[7];
    const float* txt_ln_g = (const float*)d_in[8];
    const float* txt_ln_b = (const float*)d_in[9];
    const float* gate_w1  = (const float*)d_in[10];
    const float* gate_b1  = (const float*)d_in[11];
    const float* gate_w2  = (const float*)d_in[12];
    const float* gate_b2  = (const float*)d_in[13];
    const float* gate_w3  = (const float*)d_in[14];
    const float* gate_b3  = (const float*)d_in[15];
    const float* in_proj_w  = (const float*)d_in[16];
    const float* conv_w     = (const float*)d_in[17];
    const float* conv_b     = (const float*)d_in[18];
    const float* x_proj_w   = (const float*)d_in[19];
    const float* dt_proj_w  = (const float*)d_in[20];
    const float* dt_proj_b  = (const float*)d_in[21];
    /* d_in[22] = A_log: unused (L=1, h0=0) */
    const float* D_param    = (const float*)d_in[23];
    const float* out_proj_w = (const float*)d_in[24];
    const float* mnorm_g    = (const float*)d_in[25];
    const float* mnorm_b    = (const float*)d_in[26];
    const float* fc_w    = (const float*)d_in[27];
    const float* fc_b    = (const float*)d_in[28];
    const float* final_g = (const float*)d_in[29];
    const float* final_b = (const float*)d_in[30];

    float* out_fused = (float*)d_out;
    float* out_gate  = (float*)d_out + (size_t)BATCH * 256;

    float *cat, *x, *tA2, *h2, *xz, *xc, *dbc, *bcd, *mo, *fcb;
    cudaGetSymbolAddress((void**)&cat, g_cat);
    cudaGetSymbolAddress((void**)&x,   g_x);
    cudaGetSymbolAddress((void**)&tA2, g_tA2);
    cudaGetSymbolAddress((void**)&h2,  g_h2);
    cudaGetSymbolAddress((void**)&xz,  g_xz);
    cudaGetSymbolAddress((void**)&xc,  g_xc);
    cudaGetSymbolAddress((void**)&dbc, g_dbc);
    cudaGetSymbolAddress((void**)&bcd, g_bcd);
    cudaGetSymbolAddress((void**)&mo,  g_mo);
    cudaGetSymbolAddress((void**)&fcb, g_fc);

    __half *wimg, *wtxt, *wg1, *wg2, *winp, *wxp, *wdt, *wop, *wfc;
    __half *feat16, *tB216, *cat16, *h116, *x16, *xc16, *dbc16, *u16;
    cudaGetSymbolAddress((void**)&wimg, h_wimg);
    cudaGetSymbolAddress((void**)&wtxt, h_wtxt);
    cudaGetSymbolAddress((void**)&wg1,  h_wg1);
    cudaGetSymbolAddress((void**)&wg2,  h_wg2);
    cudaGetSymbolAddress((void**)&winp, h_winp);
    cudaGetSymbolAddress((void**)&wxp,  h_wxp);
    cudaGetSymbolAddress((void**)&wdt,  h_wdt);
    cudaGetSymbolAddress((void**)&wop,  h_wop);
    cudaGetSymbolAddress((void**)&wfc,  h_wfc);
    cudaGetSymbolAddress((void**)&feat16, h_feat);
    cudaGetSymbolAddress((void**)&tB216,  h_tB2);
    cudaGetSymbolAddress((void**)&cat16,  h_cat);
    cudaGetSymbolAddress((void**)&h116,   h_h1);
    cudaGetSymbolAddress((void**)&x16,    h_x);
    cudaGetSymbolAddress((void**)&xc16,   h_xc);
    cudaGetSymbolAddress((void**)&dbc16,  h_dbc);
    cudaGetSymbolAddress((void**)&u16,    h_u);

    cudaFuncSetAttribute(gemm_mma<EPI_NONE>,
                         cudaFuncAttributeMaxDynamicSharedMemorySize, MM_SMEM_BYTES);
    cudaFuncSetAttribute(gemm_mma<EPI_RELU>,
                         cudaFuncAttributeMaxDynamicSharedMemorySize, MM_SMEM_BYTES);
    cudaFuncSetAttribute(gemm_mma<EPI_BIAS>,
                         cudaFuncAttributeMaxDynamicSharedMemorySize, MM_SMEM_BYTES);
    cudaFuncSetAttribute(gemm_mma<EPI_INPROJ>,
                         cudaFuncAttributeMaxDynamicSharedMemorySize, MM_SMEM_BYTES);
    cudaFuncSetAttribute(gemm_mma<EPI_SSM>,
                         cudaFuncAttributeMaxDynamicSharedMemorySize, MM_SMEM_BYTES);

    // ---- convert all weights + input features to fp16 (one kernel) ----
    {
        ConvArgs a;
        const float* srcs[NSEG] = {img_w, txt_w, gate_w1, gate_w2, in_proj_w,
                                   x_proj_w, dt_proj_w, out_proj_w, fc_w,
                                   image_features, text_features};
        __half* dsts[NSEG] = {wimg, wtxt, wg1, wg2, winp, wxp, wdt, wop, wfc,
                              feat16, feat16 + (size_t)BATCH * DIMD};
        int cnt4[NSEG] = {
            3 * DIMD * DIMD / 4, 3 * DIMD * DIMD / 4,
            DIMD * DM / 4, 256 * DIMD / 4,
            3 * (2 * DI) * DM / 4, 3 * 96 * DI / 4, 3 * DI * DTR / 4,
            3 * DM * DI / 4, 256 * DM / 4,
            BATCH * DIMD / 4, BATCH * DIMD / 4};
        int acc = 0;
        for (int i = 0; i < NSEG; i++) {
            a.src[i] = (const float4*)srcs[i];
            a.dst[i] = dsts[i];
            a.off[i] = acc;
            acc += cnt4[i];
        }
        a.off[NSEG] = acc;
        conv_half_kernel<<<2048, 256>>>(a, acc);
    }

    // ---- align: 3x batched (img+txt) gemm+relu -> LN ----
    for (int i = 0; i < 3; i++) {
        gemm_mma<EPI_RELU><<<tgrid(2 * BATCH, DIMD), 256, MM_SMEM_BYTES>>>(
            (i == 0) ? feat16 : tB216,
            wimg + (size_t)i * DIMD * DIMD, wtxt + (size_t)i * DIMD * DIMD, BATCH,
            2 * BATCH, DIMD, DIMD, DIMD,
            tA2, nullptr, img_b + (size_t)i * DIMD, txt_b + (size_t)i * DIMD,
            nullptr, nullptr, nullptr, nullptr, nullptr, nullptr);
        if (i < 2) {
            ln_warp2<<<256, 256>>>(tA2, nullptr, nullptr,
                                   tB216, tB216 + (size_t)BATCH * DIMD,
                                   img_ln_g + (size_t)i * DIMD, img_ln_b + (size_t)i * DIMD,
                                   txt_ln_g + (size_t)i * DIMD, txt_ln_b + (size_t)i * DIMD,
                                   DIMD, DIMD);
        } else {
            ln_warp2<<<256, 256>>>(tA2, cat, cat + DIMD,
                                   cat16, cat16 + DIMD,
                                   img_ln_g + (size_t)i * DIMD, img_ln_b + (size_t)i * DIMD,
                                   txt_ln_g + (size_t)i * DIMD, txt_ln_b + (size_t)i * DIMD,
                                   DM, DM);
        }
    }

    // ---- gate MLP -> softmax -> build x ----
    gemm_mma<EPI_RELU><<<tgrid(BATCH, DIMD), 256, MM_SMEM_BYTES>>>(
        cat16, wg1, nullptr, MBIG, BATCH, DIMD, DM, DM,
        nullptr, h116, gate_b1, nullptr,
        nullptr, nullptr, nullptr, nullptr, nullptr, nullptr);
    gemm_mma<EPI_RELU><<<tgrid(BATCH, 256), 256, MM_SMEM_BYTES>>>(
        h116, wg2, nullptr, MBIG, BATCH, 256, DIMD, DIMD,
        h2, nullptr, gate_b2, nullptr,
        nullptr, nullptr, nullptr, nullptr, nullptr, nullptr);
    gate_kernel<<<BATCH, 128>>>(x, x16, out_gate, h2, cat, gate_w3, gate_b3);

    // ---- 3 mamba layers (L=1 collapsed) ----
    for (int l = 0; l < 3; l++) {
        gemm_mma<EPI_INPROJ><<<tgrid(BATCH, 2 * DI), 256, MM_SMEM_BYTES>>>(
            x16, winp + (size_t)l * (2 * DI) * DM, nullptr, MBIG,
            BATCH, 2 * DI, DM, DM,
            xz, nullptr, nullptr, nullptr,
            xc, xc16, conv_w + (size_t)l * DI * 4, conv_b + (size_t)l * DI,
            nullptr, nullptr);
        gemm_mma<EPI_NONE><<<tgrid(BATCH, 96), 256, MM_SMEM_BYTES>>>(
            xc16, wxp + (size_t)l * 96 * DI, nullptr, MBIG,
            BATCH, 96, DI, DI,
            dbc, dbc16, nullptr, nullptr,
            nullptr, nullptr, nullptr, nullptr, nullptr, nullptr);
        bcdot_kernel<<<4, 256>>>(bcd, dbc);
        gemm_mma<EPI_SSM><<<tgrid(BATCH, DI), 256, MM_SMEM_BYTES>>>(
            dbc16, wdt + (size_t)l * DI * DTR, nullptr, MBIG,
            BATCH, DI, DTR, 96,
            nullptr, u16, dt_proj_b + (size_t)l * DI, nullptr,
            nullptr, nullptr, xc, xz, bcd, D_param + (size_t)l * DI);
        gemm_mma<EPI_NONE><<<tgrid(BATCH, DM), 256, MM_SMEM_BYTES>>>(
            u16, wop + (size_t)l * DM * DI, nullptr, MBIG,
            BATCH, DM, DI, DI,
            mo, nullptr, nullptr, nullptr,
            nullptr, nullptr, nullptr, nullptr, nullptr, nullptr);
        ln_warp<<<128, 256>>>(x, x16, mo, x,
                              mnorm_g + (size_t)l * DM, mnorm_b + (size_t)l * DM,
                              DM, DM, DM, BATCH);
    }

    // ---- final fc + LN -> fused output ----
    gemm_mma<EPI_BIAS><<<tgrid(BATCH, 256), 256, MM_SMEM_BYTES>>>(
        x16, wfc, nullptr, MBIG, BATCH, 256, DM, DM,
        fcb, nullptr, fc_b, nullptr,
        nullptr, nullptr, nullptr, nullptr, nullptr, nullptr);
    ln_warp<<<128, 256>>>(out_fused, nullptr, fcb, nullptr,
                          final_g, final_b, 256, 256, 256, BATCH);
}

// round 11
// speedup vs baseline: 3.3579x; 1.1825x over previous
#include <cuda_runtime.h>
#include <cuda_fp16.h>
#include <cstdint>
#include <math.h>

#define BATCH 1024
#define DIMD  512
#define DM    1024
#define DI    2048
#define DTR   64
#define DS    16

// ---------------- static fp32 scratch ----------------
__device__ float g_cat [BATCH * DM];
__device__ float g_x   [BATCH * DM];
__device__ float g_tA2 [2 * BATCH * DIMD];
__device__ float g_h2  [BATCH * 256];
__device__ float g_xz  [BATCH * (2 * DI)];
__device__ float g_xc  [BATCH * DI];
__device__ float g_dbcp[4 * BATCH * 96];    // x_proj split-K partials
__device__ float g_bcd [BATCH];
__device__ float g_mo2 [2 * BATCH * DM];    // out_proj split-K partials
__device__ float g_fcp [4 * BATCH * 256];   // fc split-K partials

// ---------------- static fp16 scratch ----------------
__device__ __half h_wimg[3 * DIMD * DIMD];
__device__ __half h_wtxt[3 * DIMD * DIMD];
__device__ __half h_wg1 [DIMD * DM];
__device__ __half h_wg2 [256 * DIMD];
__device__ __half h_winp[3 * (2 * DI) * DM];
__device__ __half h_wxp [3 * 96 * DI];
__device__ __half h_wdt [3 * DI * DTR];
__device__ __half h_wop [3 * DM * DI];
__device__ __half h_wfc [256 * DM];
__device__ __half h_feat[2 * BATCH * DIMD];
__device__ __half h_tB2 [2 * BATCH * DIMD];
__device__ __half h_cat [BATCH * DM];
__device__ __half h_h1  [BATCH * DIMD];
__device__ __half h_x   [BATCH * DM];
__device__ __half h_xc  [BATCH * DI];
__device__ __half h_dbc [BATCH * 96];
__device__ __half h_u   [BATCH * DI];

// ---------------- helpers ----------------
__device__ __forceinline__ float siluf(float x) { return x / (1.f + expf(-x)); }
__device__ __forceinline__ float softplusf_(float x) { return x > 20.f ? x : log1pf(expf(x)); }

enum { EPI_NONE = 0, EPI_RELU = 1, EPI_BIAS = 2, EPI_INPROJ = 4, EPI_SSM = 5, EPI_PART = 6 };

__device__ __forceinline__ uint32_t smem_to_u32(const void* p) {
    uint32_t a;
    asm("{ .reg .u64 tmp; cvta.to.shared.u64 tmp, %1; cvt.u32.u64 %0, tmp; }"
        : "=r"(a) : "l"(p));
    return a;
}
#define SMEM_SWIZZLE_128B(byte_offset) \
    ((byte_offset) ^ (((byte_offset) >> 3) & 0x70))

__device__ __forceinline__ void mma_f16(float* c, const uint32_t* a, const uint32_t* b) {
    asm volatile(
        "mma.sync.aligned.m16n8k16.row.col.f32.f16.f16.f32 "
        "{%0,%1,%2,%3}, {%4,%5,%6,%7}, {%8,%9}, {%0,%1,%2,%3};"
        : "+f"(c[0]), "+f"(c[1]), "+f"(c[2]), "+f"(c[3])
        : "r"(a[0]), "r"(a[1]), "r"(a[2]), "r"(a[3]), "r"(b[0]), "r"(b[1]));
}
__device__ __forceinline__ void ldsm4(uint32_t* r, uint32_t addr) {
    asm volatile("ldmatrix.sync.aligned.m8n8.x4.shared.b16 {%0,%1,%2,%3}, [%4];"
                 : "=r"(r[0]), "=r"(r[1]), "=r"(r[2]), "=r"(r[3]) : "r"(addr));
}
__device__ __forceinline__ void cp_async16(uint32_t dst, const void* src, uint32_t sz) {
    asm volatile("cp.async.ca.shared.global [%0], [%1], 16, %2;"
                 :: "r"(dst), "l"(src), "r"(sz));
}

// ================= fp32 -> fp16 batch conversion =========================
#define NSEG 11
struct ConvArgs {
    const float4* src[NSEG];
    __half* dst[NSEG];
    int off[NSEG + 1];
};
__global__ void __launch_bounds__(256) conv_half_kernel(ConvArgs a, int total4)
{
    for (int idx = blockIdx.x * 256 + threadIdx.x; idx < total4;
         idx += gridDim.x * 256) {
        int seg = 0;
#pragma unroll
        for (int s = 1; s < NSEG; s++) if (idx >= a.off[s]) seg = s;
        int j = idx - a.off[seg];
        float4 v = a.src[seg][j];
        __half2* d = (__half2*)(a.dst[seg] + (size_t)j * 4);
        d[0] = __floats2half2_rn(v.x, v.y);
        d[1] = __floats2half2_rn(v.z, v.w);
    }
}

// ================= fp16 tensor-core GEMM =================================
// C = act(A[M,K] @ W[N,K]^T + bias)
// CTA 128x64, BK=64, 8 warps (warp tile 32x32), 3-stage cp.async pipeline.
// SMEM stage: A 16KB + B 8KB = 24KB; 3 stages = 72KB.
// Split-K via blockIdx.z (Ksplit = K / gridDim.z); EPI_PART writes partials.
static constexpr int STAGE_BYTES = 24576;
static constexpr int MM_SMEM_BYTES = 3 * STAGE_BYTES;

template <int EPI>
__global__ void __launch_bounds__(256) gemm_mma(
    const __half* __restrict__ A, const __half* __restrict__ Wm,
    const __half* __restrict__ Wm2, int Msplit,
    int M, int N, int K, int lda, int Ksplit,
    float* __restrict__ C, __half* __restrict__ C16,
    const float* __restrict__ bias, const float* __restrict__ bias2,
    float* __restrict__ X, __half* __restrict__ X16,
    const float* __restrict__ p0, const float* __restrict__ p1,
    const float* __restrict__ p2, const float* __restrict__ p3)
{
    extern __shared__ char smem[];
    const uint32_t sb = smem_to_u32(smem);
    const int tid = threadIdx.x;
    const int lane = tid & 31;
    const int wid = tid >> 5;
    const int wm = wid & 3;        // 4 m-subtiles of 32
    const int wn = wid >> 2;       // 2 n-subtiles of 32
    const int mBase = blockIdx.y * 128;
    const int nBase = blockIdx.x * 64;
    const int z = blockIdx.z;
    const int kOff = z * Ksplit;
    const int nch = Ksplit >> 6;

    const __half* Wsel = (mBase >= Msplit) ? Wm2 : Wm;
    const float* bsel  = (mBase >= Msplit) ? bias2 : bias;

    // ---- loader: 1536 16B segs (A:1024, B:512), 6 per thread ----
    const __half* gp[6];
    uint32_t dof[6], gsz[6];
#pragma unroll
    for (int j = 0; j < 6; j++) {
        int flat = tid * 6 + j;
        if (flat < 1024) {
            int arow = flat >> 3, acol = flat & 7;
            gp[j] = A + (size_t)(mBase + arow) * lda + kOff + acol * 8;
            dof[j] = SMEM_SWIZZLE_128B((uint32_t)arow * 128u + (uint32_t)acol * 16u);
            gsz[j] = 16;
        } else {
            int f2 = flat - 1024;
            int brow = f2 >> 3, bcol = f2 & 7;
            int grow = nBase + brow;
            gp[j] = Wsel + (size_t)(grow < N ? grow : 0) * K + kOff + bcol * 8;
            dof[j] = 16384u + SMEM_SWIZZLE_128B((uint32_t)brow * 128u + (uint32_t)bcol * 16u);
            gsz[j] = (grow < N) ? 16 : 0;
        }
    }

    // ldmatrix address components
    const uint32_t a_rowc = (uint32_t)(wm * 32 + (lane & 15));
    const uint32_t a_cb   = ((uint32_t)(lane >> 4)) * 16u;
    const uint32_t a_x    = (a_rowc & 7u) << 4;
    const uint32_t b_rowc = (uint32_t)(wn * 32 + (lane & 7) + ((lane >> 4) & 1) * 8);
    const uint32_t b_cb   = ((uint32_t)((lane >> 3) & 1)) * 16u;
    const uint32_t b_x    = ((uint32_t)(lane & 7)) << 4;

    float acc[2][4][4];
#pragma unroll
    for (int mf = 0; mf < 2; mf++)
#pragma unroll
        for (int nf = 0; nf < 4; nf++)
#pragma unroll
            for (int q = 0; q < 4; q++) acc[mf][nf][q] = 0.f;

    // ---- prologue: stage 0,1 ----
#pragma unroll
    for (int c = 0; c < 2; c++) {
        if (c < nch) {
            uint32_t base = sb + (uint32_t)c * STAGE_BYTES;
#pragma unroll
            for (int j = 0; j < 6; j++)
                cp_async16(base + dof[j], gp[j] + c * 64, gsz[j]);
        }
        asm volatile("cp.async.commit_group;");
    }

    for (int ch = 0; ch < nch; ch++) {
        asm volatile("cp.async.wait_group 1;");
        __syncthreads();

        const int nxt = ch + 2;
        if (nxt < nch) {
            uint32_t base = sb + (uint32_t)(nxt % 3) * STAGE_BYTES;
#pragma unroll
            for (int j = 0; j < 6; j++)
                cp_async16(base + dof[j], gp[j] + nxt * 64, gsz[j]);
        }
        asm volatile("cp.async.commit_group;");

        const uint32_t aAddr = sb + (uint32_t)(ch % 3) * STAGE_BYTES;
        const uint32_t bAddr = aAddr + 16384u;
#pragma unroll
        for (int ks = 0; ks < 4; ks++) {
            uint32_t Af[2][4], Bf[2][4];
#pragma unroll
            for (int mf = 0; mf < 2; mf++)
                ldsm4(Af[mf], aAddr + (a_rowc + (uint32_t)mf * 16u) * 128u +
                              (((uint32_t)ks * 32u + a_cb) ^ a_x));
#pragma unroll
            for (int p = 0; p < 2; p++)
                ldsm4(Bf[p], bAddr + (b_rowc + (uint32_t)p * 16u) * 128u +
                             (((uint32_t)ks * 32u + b_cb) ^ b_x));
#pragma unroll
            for (int mf = 0; mf < 2; mf++)
#pragma unroll
                for (int p = 0; p < 2; p++) {
                    mma_f16(acc[mf][p * 2 + 0], Af[mf], &Bf[p][0]);
                    mma_f16(acc[mf][p * 2 + 1], Af[mf], &Bf[p][2]);
                }
        }
    }

    // ---- epilogue ----
    float* Cz = C;
    if (EPI == EPI_PART) Cz = C + (size_t)z * M * N;
    const int mrow0 = mBase + wm * 32 + (lane >> 2);
    const int ncol00 = nBase + wn * 32 + (lane & 3) * 2;
    const int colOff[4] = {0, 8, 16, 24};
#pragma unroll
    for (int mf = 0; mf < 2; mf++) {
        const int r0 = mrow0 + mf * 16;
        const int r1 = r0 + 8;
#pragma unroll
        for (int nf = 0; nf < 4; nf++) {
            const int col = ncol00 + colOff[nf];
            if (col >= N) continue;
            float v0 = acc[mf][nf][0], v1 = acc[mf][nf][1];
            float v2 = acc[mf][nf][2], v3 = acc[mf][nf][3];

            if (EPI == EPI_PART) {
                float2 o0; o0.x = v0; o0.y = v1;
                float2 o1; o1.x = v2; o1.y = v3;
                *(float2*)(Cz + (size_t)r0 * N + col) = o0;
                *(float2*)(Cz + (size_t)r1 * N + col) = o1;
            } else if (EPI == EPI_INPROJ) {
                float2 o0; o0.x = v0; o0.y = v1;
                float2 o1; o1.x = v2; o1.y = v3;
                *(float2*)(C + (size_t)r0 * N + col) = o0;
                *(float2*)(C + (size_t)r1 * N + col) = o1;
                if (col < DI) {
                    float w0 = p0[col * 4 + 3], w1 = p0[(col + 1) * 4 + 3];
                    float cb0 = p1[col], cb1 = p1[col + 1];
                    float x0 = siluf(v0 * w0 + cb0), x1 = siluf(v1 * w1 + cb1);
                    float x2 = siluf(v2 * w0 + cb0), x3 = siluf(v3 * w1 + cb1);
                    float2 a0; a0.x = x0; a0.y = x1;
                    float2 a1; a1.x = x2; a1.y = x3;
                    *(float2*)(X + (size_t)r0 * DI + col) = a0;
                    *(float2*)(X + (size_t)r1 * DI + col) = a1;
                    *(__half2*)(X16 + (size_t)r0 * DI + col) = __floats2half2_rn(x0, x1);
                    *(__half2*)(X16 + (size_t)r1 * DI + col) = __floats2half2_rn(x2, x3);
                }
            } else if (EPI == EPI_SSM) {
                float bb0 = bsel[col], bb1 = bsel[col + 1];
                float d0 = softplusf_(v0 + bb0), d1 = softplusf_(v1 + bb1);
                float d2 = softplusf_(v2 + bb0), d3 = softplusf_(v3 + bb1);
                float D0 = p3[col], D1 = p3[col + 1];
                float bc0 = p2[r0], bc1 = p2[r1];
                float2 xcA = *(const float2*)(p0 + (size_t)r0 * DI + col);
                float2 xcB = *(const float2*)(p0 + (size_t)r1 * DI + col);
                float2 zA = *(const float2*)(p1 + (size_t)r0 * (2 * DI) + DI + col);
                float2 zB = *(const float2*)(p1 + (size_t)r1 * (2 * DI) + DI + col);
                float u0 = xcA.x * (d0 * bc0 + D0) * siluf(zA.x);
                float u1 = xcA.y * (d1 * bc0 + D1) * siluf(zA.y);
                float u2 = xcB.x * (d2 * bc1 + D0) * siluf(zB.x);
                float u3 = xcB.y * (d3 * bc1 + D1) * siluf(zB.y);
                *(__half2*)(C16 + (size_t)r0 * N + col) = __floats2half2_rn(u0, u1);
                *(__half2*)(C16 + (size_t)r1 * N + col) = __floats2half2_rn(u2, u3);
            } else {
                if (EPI == EPI_RELU || EPI == EPI_BIAS) {
                    float bx = bsel[col], by = bsel[col + 1];
                    v0 += bx; v1 += by; v2 += bx; v3 += by;
                }
                if (EPI == EPI_RELU) {
                    v0 = fmaxf(v0, 0.f); v1 = fmaxf(v1, 0.f);
                    v2 = fmaxf(v2, 0.f); v3 = fmaxf(v3, 0.f);
                }
                if (C) {
                    float2 o0; o0.x = v0; o0.y = v1;
                    float2 o1; o1.x = v2; o1.y = v3;
                    *(float2*)(C + (size_t)r0 * N + col) = o0;
                    *(float2*)(C + (size_t)r1 * N + col) = o1;
                }
                if (C16) {
                    *(__half2*)(C16 + (size_t)r0 * N + col) = __floats2half2_rn(v0, v1);
                    *(__half2*)(C16 + (size_t)r1 * N + col) = __floats2half2_rn(v2, v3);
                }
            }
        }
    }
}

// ================= warp-per-row layernorm (with split-K reduce) ==========
__global__ void __launch_bounds__(256) ln_warp(
    float* __restrict__ out, __half* __restrict__ out16,
    const float* __restrict__ in, int S, size_t sstr,
    const float* __restrict__ res,
    const float* __restrict__ g, const float* __restrict__ b,
    int W, int ostride, int o16stride, int rows)
{
    const int gw = (blockIdx.x * blockDim.x + threadIdx.x) >> 5;
    const int lane = threadIdx.x & 31;
    if (gw >= rows) return;
    const int nv = W >> 7;
    float4 v[8];
    float s = 0.f, q = 0.f;
#pragma unroll 8
    for (int i = 0; i < nv; i++) {
        const int i4 = lane + i * 32;
        float4 t = ((const float4*)(in + (size_t)gw * W))[i4];
        for (int sp = 1; sp < S; sp++) {
            float4 t2 = ((const float4*)(in + sp * sstr + (size_t)gw * W))[i4];
            t.x += t2.x; t.y += t2.y; t.z += t2.z; t.w += t2.w;
        }
        if (res) {
            float4 r2 = ((const float4*)(res + (size_t)gw * W))[i4];
            t.x += r2.x; t.y += r2.y; t.z += r2.z; t.w += r2.w;
        }
        v[i] = t;
        s += t.x + t.y + t.z + t.w;
        q += t.x * t.x + t.y * t.y + t.z * t.z + t.w * t.w;
    }
#pragma unroll
    for (int o = 16; o > 0; o >>= 1) {
        s += __shfl_xor_sync(0xffffffffu, s, o);
        q += __shfl_xor_sync(0xffffffffu, q, o);
    }
    const float m = s / (float)W;
    const float r = rsqrtf(q / (float)W - m * m + 1e-5f);
#pragma unroll 8
    for (int i = 0; i < nv; i++) {
        const int i4 = lane + i * 32;
        float4 gg = ((const float4*)g)[i4];
        float4 bb = ((const float4*)b)[i4];
        float4 o;
        o.x = (v[i].x - m) * r * gg.x + bb.x;
        o.y = (v[i].y - m) * r * gg.y + bb.y;
        o.z = (v[i].z - m) * r * gg.z + bb.z;
        o.w = (v[i].w - m) * r * gg.w + bb.w;
        if (out) ((float4*)(out + (size_t)gw * ostride))[i4] = o;
        if (out16) {
            __half2* hp = (__half2*)(out16 + (size_t)gw * o16stride + i4 * 4);
            hp[0] = __floats2half2_rn(o.x, o.y);
            hp[1] = __floats2half2_rn(o.z, o.w);
        }
    }
}

// batched align LN: rows 0-1023 = img set, 1024-2047 = txt set (W=512)
__global__ void __launch_bounds__(256) ln_warp2(
    const float* __restrict__ in,
    float* __restrict__ out0, float* __restrict__ out1,
    __half* __restrict__ o16a, __half* __restrict__ o16b,
    const float* __restrict__ g0, const float* __restrict__ b0,
    const float* __restrict__ g1, const float* __restrict__ b1,
    int ostride, int o16stride)
{
    const int gw = (blockIdx.x * blockDim.x + threadIdx.x) >> 5;
    const int lane = threadIdx.x & 31;
    if (gw >= 2048) return;
    const int set = gw >> 10;
    const int rr = gw & 1023;
    const float* g = set ? g1 : g0;
    const float* b = set ? b1 : b0;
    float* out = set ? out1 : out0;
    __half* o16 = set ? o16b : o16a;
    const float4* ip = (const float4*)(in + (size_t)gw * 512);
    float4 v[4];
    float s = 0.f, q = 0.f;
#pragma unroll
    for (int i = 0; i < 4; i++) {
        float4 t = ip[lane + i * 32];
        v[i] = t;
        s += t.x + t.y + t.z + t.w;
        q += t.x * t.x + t.y * t.y + t.z * t.z + t.w * t.w;
    }
#pragma unroll
    for (int o = 16; o > 0; o >>= 1) {
        s += __shfl_xor_sync(0xffffffffu, s, o);
        q += __shfl_xor_sync(0xffffffffu, q, o);
    }
    const float m = s / 512.f;
    const float r = rsqrtf(q / 512.f - m * m + 1e-5f);
#pragma unroll
    for (int i = 0; i < 4; i++) {
        const int i4 = lane + i * 32;
        float4 gg = ((const float4*)g)[i4];
        float4 bb = ((const float4*)b)[i4];
        float4 o;
        o.x = (v[i].x - m) * r * gg.x + bb.x;
        o.y = (v[i].y - m) * r * gg.y + bb.y;
        o.z = (v[i].z - m) * r * gg.z + bb.z;
        o.w = (v[i].w - m) * r * gg.w + bb.w;
        if (out) ((float4*)(out + (size_t)rr * ostride))[i4] = o;
        if (o16) {
            __half2* hp = (__half2*)(o16 + (size_t)rr * o16stride + i4 * 4);
            hp[0] = __floats2half2_rn(o.x, o.y);
            hp[1] = __floats2half2_rn(o.z, o.w);
        }
    }
}

// ---------------- gate head ----------------
__global__ void __launch_bounds__(128) gate_kernel(
    float* __restrict__ x, __half* __restrict__ x16,
    float* __restrict__ gate_out, const float* __restrict__ h2,
    const float* __restrict__ cat, const float* __restrict__ w3,
    const float* __restrict__ b3)
{
    const int bi = blockIdx.x;
    const int t = threadIdx.x;
    const float* h = h2 + (size_t)bi * 256;
    float p0 = 0.f, p1 = 0.f;
    for (int i = t; i < 256; i += 128) {
        float hv = h[i];
        p0 += hv * w3[i];
        p1 += hv * w3[256 + i];
    }
    __shared__ float s0[4], s1[4];
    for (int o = 16; o > 0; o >>= 1) {
        p0 += __shfl_down_sync(0xffffffffu, p0, o);
        p1 += __shfl_down_sync(0xffffffffu, p1, o);
    }
    if ((t & 31) == 0) { s0[t >> 5] = p0; s1[t >> 5] = p1; }
    __syncthreads();
    __shared__ float g0s, g1s;
    if (t == 0) {
        float l0 = s0[0] + s0[1] + s0[2] + s0[3] + b3[0];
        float l1 = s1[0] + s1[1] + s1[2] + s1[3] + b3[1];
        float mx = fmaxf(l0, l1);
        float e0 = expf(l0 - mx), e1 = expf(l1 - mx);
        float inv = 1.f / (e0 + e1);
        g0s = e0 * inv; g1s = e1 * inv;
        gate_out[bi * 2 + 0] = g0s;
        gate_out[bi * 2 + 1] = g1s;
    }
    __syncthreads();
    const float g0 = g0s, g1 = g1s;
    const float* c = cat + (size_t)bi * DM;
    float* xo = x + (size_t)bi * DM;
    __half* xo16 = x16 + (size_t)bi * DM;
    for (int i = t; i < DM; i += 128) {
        float val = c[i] * (i < DIMD ? g0 : g1);
        xo[i] = val;
        xo16[i] = __float2half(val);
    }
}

// -------- x_proj split-K reduce + Bc.Cc dot + fp16 convert --------
__global__ void __launch_bounds__(128) bcdot_kernel(
    float* __restrict__ bcd, __half* __restrict__ dbc16,
    const float* __restrict__ part)   // [4][BATCH][96]
{
    const int bi = blockIdx.x;
    const int t = threadIdx.x;
    __shared__ float sh[96];
    if (t < 96) {
        float s = part[(size_t)bi * 96 + t]
                + part[(size_t)BATCH * 96 + (size_t)bi * 96 + t]
                + part[(size_t)2 * BATCH * 96 + (size_t)bi * 96 + t]
                + part[(size_t)3 * BATCH * 96 + (size_t)bi * 96 + t];
        sh[t] = s;
        dbc16[(size_t)bi * 96 + t] = __float2half(s);
    }
    __syncthreads();
    if (t == 0) {
        float s = 0.f;
#pragma unroll
        for (int i = 0; i < DS; i++) s += sh[64 + i] * sh[80 + i];
        bcd[bi] = s;
    }
}

// ---------------- launch ----------------
static inline dim3 tgrid(int M, int N, int S = 1) {
    return dim3((N + 63) / 64, M / 128, S);
}
static constexpr int MBIG = 1 << 30;

extern "C" void kernel_launch(void* const* d_in, const int* in_sizes, int n_in,
                              void* d_out, int out_size)
{
    const float* image_features = (const float*)d_in[0];
    const float* text_features  = (const float*)d_in[1];
    const float* img_w    = (const float*)d_in[2];
    const float* img_b    = (const float*)d_in[3];
    const float* img_ln_g = (const float*)d_in[4];
    const float* img_ln_b = (const float*)d_in[5];
    const float* txt_w    = (const float*)d_in[6];
    const float* txt_b    = (const float*)d_in[7];
    const float* txt_ln_g = (const float*)d_in[8];
    const float* txt_ln_b = (const float*)d_in[9];
    const float* gate_w1  = (const float*)d_in[10];
    const float* gate_b1  = (const float*)d_in[11];
    const float* gate_w2  = (const float*)d_in[12];
    const float* gate_b2  = (const float*)d_in[13];
    const float* gate_w3  = (const float*)d_in[14];
    const float* gate_b3  = (const float*)d_in[15];
    const float* in_proj_w  = (const float*)d_in[16];
    const float* conv_w     = (const float*)d_in[17];
    const float* conv_b     = (const float*)d_in[18];
    const float* x_proj_w   = (const float*)d_in[19];
    const float* dt_proj_w  = (const float*)d_in[20];
    const float* dt_proj_b  = (const float*)d_in[21];
    /* d_in[22] = A_log: unused (L=1, h0=0) */
    const float* D_param    = (const float*)d_in[23];
    const float* out_proj_w = (const float*)d_in[24];
    const float* mnorm_g    = (const float*)d_in[25];
    const float* mnorm_b    = (const float*)d_in[26];
    const float* fc_w    = (const float*)d_in[27];
    const float* fc_b    = (const float*)d_in[28];
    const float* final_g = (const float*)d_in[29];
    const float* final_b = (const float*)d_in[30];

    float* out_fused = (float*)d_out;
    float* out_gate  = (float*)d_out + (size_t)BATCH * 256;

    float *cat, *x, *tA2, *h2, *xz, *xc, *dbcp, *bcd, *mo2, *fcp;
    cudaGetSymbolAddress((void**)&cat,  g_cat);
    cudaGetSymbolAddress((void**)&x,    g_x);
    cudaGetSymbolAddress((void**)&tA2,  g_tA2);
    cudaGetSymbolAddress((void**)&h2,   g_h2);
    cudaGetSymbolAddress((void**)&xz,   g_xz);
    cudaGetSymbolAddress((void**)&xc,   g_xc);
    cudaGetSymbolAddress((void**)&dbcp, g_dbcp);
    cudaGetSymbolAddress((void**)&bcd,  g_bcd);
    cudaGetSymbolAddress((void**)&mo2,  g_mo2);
    cudaGetSymbolAddress((void**)&fcp,  g_fcp);

    __half *wimg, *wtxt, *wg1, *wg2, *winp, *wxp, *wdt, *wop, *wfc;
    __half *feat16, *tB216, *cat16, *h116, *x16, *xc16, *dbc16, *u16;
    cudaGetSymbolAddress((void**)&wimg, h_wimg);
    cudaGetSymbolAddress((void**)&wtxt, h_wtxt);
    cudaGetSymbolAddress((void**)&wg1,  h_wg1);
    cudaGetSymbolAddress((void**)&wg2,  h_wg2);
    cudaGetSymbolAddress((void**)&winp, h_winp);
    cudaGetSymbolAddress((void**)&wxp,  h_wxp);
    cudaGetSymbolAddress((void**)&wdt,  h_wdt);
    cudaGetSymbolAddress((void**)&wop,  h_wop);
    cudaGetSymbolAddress((void**)&wfc,  h_wfc);
    cudaGetSymbolAddress((void**)&feat16, h_feat);
    cudaGetSymbolAddress((void**)&tB216,  h_tB2);
    cudaGetSymbolAddress((void**)&cat16,  h_cat);
    cudaGetSymbolAddress((void**)&h116,   h_h1);
    cudaGetSymbolAddress((void**)&x16,    h_x);
    cudaGetSymbolAddress((void**)&xc16,   h_xc);
    cudaGetSymbolAddress((void**)&dbc16,  h_dbc);
    cudaGetSymbolAddress((void**)&u16,    h_u);

    cudaFuncSetAttribute(gemm_mma<EPI_RELU>,
                         cudaFuncAttributeMaxDynamicSharedMemorySize, MM_SMEM_BYTES);
    cudaFuncSetAttribute(gemm_mma<EPI_INPROJ>,
                         cudaFuncAttributeMaxDynamicSharedMemorySize, MM_SMEM_BYTES);
    cudaFuncSetAttribute(gemm_mma<EPI_SSM>,
                         cudaFuncAttributeMaxDynamicSharedMemorySize, MM_SMEM_BYTES);
    cudaFuncSetAttribute(gemm_mma<EPI_PART>,
                         cudaFuncAttributeMaxDynamicSharedMemorySize, MM_SMEM_BYTES);

    // ---- convert all weights + input features to fp16 (one kernel) ----
    {
        ConvArgs a;
        const float* srcs[NSEG] = {img_w, txt_w, gate_w1, gate_w2, in_proj_w,
                                   x_proj_w, dt_proj_w, out_proj_w, fc_w,
                                   image_features, text_features};
        __half* dsts[NSEG] = {wimg, wtxt, wg1, wg2, winp, wxp, wdt, wop, wfc,
                              feat16, feat16 + (size_t)BATCH * DIMD};
        int cnt4[NSEG] = {
            3 * DIMD * DIMD / 4, 3 * DIMD * DIMD / 4,
            DIMD * DM / 4, 256 * DIMD / 4,
            3 * (2 * DI) * DM / 4, 3 * 96 * DI / 4, 3 * DI * DTR / 4,
            3 * DM * DI / 4, 256 * DM / 4,
            BATCH * DIMD / 4, BATCH * DIMD / 4};
        int acc = 0;
        for (int i = 0; i < NSEG; i++) {
            a.src[i] = (const float4*)srcs[i];
            a.dst[i] = dsts[i];
            a.off[i] = acc;
            acc += cnt4[i];
        }
        a.off[NSEG] = acc;
        conv_half_kernel<<<2048, 256>>>(a, acc);
    }

    // ---- align: 3x batched (img+txt) gemm+relu -> LN ----
    for (int i = 0; i < 3; i++) {
        gemm_mma<EPI_RELU><<<tgrid(2 * BATCH, DIMD), 256, MM_SMEM_BYTES>>>(
            (i == 0) ? feat16 : tB216,
            wimg + (size_t)i * DIMD * DIMD, wtxt + (size_t)i * DIMD * DIMD, BATCH,
            2 * BATCH, DIMD, DIMD, DIMD, DIMD,
            tA2, nullptr, img_b + (size_t)i * DIMD, txt_b + (size_t)i * DIMD,
            nullptr, nullptr, nullptr, nullptr, nullptr, nullptr);
        if (i < 2) {
            ln_warp2<<<256, 256>>>(tA2, nullptr, nullptr,
                                   tB216, tB216 + (size_t)BATCH * DIMD,
                                   img_ln_g + (size_t)i * DIMD, img_ln_b + (size_t)i * DIMD,
                                   txt_ln_g + (size_t)i * DIMD, txt_ln_b + (size_t)i * DIMD,
                                   DIMD, DIMD);
        } else {
            ln_warp2<<<256, 256>>>(tA2, cat, cat + DIMD,
                                   cat16, cat16 + DIMD,
                                   img_ln_g + (size_t)i * DIMD, img_ln_b + (size_t)i * DIMD,
                                   txt_ln_g + (size_t)i * DIMD, txt_ln_b + (size_t)i * DIMD,
                                   DM, DM);
        }
    }

    // ---- gate MLP -> softmax -> build x ----
    gemm_mma<EPI_RELU><<<tgrid(BATCH, DIMD), 256, MM_SMEM_BYTES>>>(
        cat16, wg1, nullptr, MBIG, BATCH, DIMD, DM, DM, DM,
        nullptr, h116, gate_b1, nullptr,
        nullptr, nullptr, nullptr, nullptr, nullptr, nullptr);
    gemm_mma<EPI_RELU><<<tgrid(BATCH, 256), 256, MM_SMEM_BYTES>>>(
        h116, wg2, nullptr, MBIG, BATCH, 256, DIMD, DIMD, DIMD,
        h2, nullptr, gate_b2, nullptr,
        nullptr, nullptr, nullptr, nullptr, nullptr, nullptr);
    gate_kernel<<<BATCH, 128>>>(x, x16, out_gate, h2, cat, gate_w3, gate_b3);

    // ---- 3 mamba layers (L=1 collapsed) ----
    for (int l = 0; l < 3; l++) {
        gemm_mma<EPI_INPROJ><<<tgrid(BATCH, 2 * DI), 256, MM_SMEM_BYTES>>>(
            x16, winp + (size_t)l * (2 * DI) * DM, nullptr, MBIG,
            BATCH, 2 * DI, DM, DM, DM,
            xz, nullptr, nullptr, nullptr,
            xc, xc16, conv_w + (size_t)l * DI * 4, conv_b + (size_t)l * DI,
            nullptr, nullptr);
        // x_proj split-K S=4 -> partials, reduce in bcdot
        gemm_mma<EPI_PART><<<tgrid(BATCH, 96, 4), 256, MM_SMEM_BYTES>>>(
            xc16, wxp + (size_t)l * 96 * DI, nullptr, MBIG,
            BATCH, 96, DI, DI, DI / 4,
            dbcp, nullptr, nullptr, nullptr,
            nullptr, nullptr, nullptr, nullptr, nullptr, nullptr);
        bcdot_kernel<<<BATCH, 128>>>(bcd, dbc16, dbcp);
        gemm_mma<EPI_SSM><<<tgrid(BATCH, DI), 256, MM_SMEM_BYTES>>>(
            dbc16, wdt + (size_t)l * DI * DTR, nullptr, MBIG,
            BATCH, DI, DTR, 96, DTR,
            nullptr, u16, dt_proj_b + (size_t)l * DI, nullptr,
            nullptr, nullptr, xc, xz, bcd, D_param + (size_t)l * DI);
        // out_proj split-K S=2 -> partials, reduce fused in residual LN
        gemm_mma<EPI_PART><<<tgrid(BATCH, DM, 2), 256, MM_SMEM_BYTES>>>(
            u16, wop + (size_t)l * DM * DI, nullptr, MBIG,
            BATCH, DM, DI, DI, DI / 2,
            mo2, nullptr, nullptr, nullptr,
            nullptr, nullptr, nullptr, nullptr, nullptr, nullptr);
        ln_warp<<<128, 256>>>(x, x16, mo2, 2, (size_t)BATCH * DM, x,
                              mnorm_g + (size_t)l * DM, mnorm_b + (size_t)l * DM,
                              DM, DM, DM, BATCH);
    }

    // ---- final fc (split-K S=4) + LN (reduce fused) -> fused output ----
    gemm_mma<EPI_PART><<<tgrid(BATCH, 256, 4), 256, MM_SMEM_BYTES>>>(
        x16, wfc, nullptr, MBIG, BATCH, 256, DM, DM, DM / 4,
        fcp, nullptr, nullptr, nullptr,
        nullptr, nullptr, nullptr, nullptr, nullptr, nullptr);
    ln_warp<<<128, 256>>>(out_fused, nullptr, fcp, 4, (size_t)BATCH * 256, nullptr,
                          final_g, final_b, 256, 256, 256, BATCH);
}

// round 12
// speedup vs baseline: 5.0526x; 1.5047x over previous
#include <cuda_runtime.h>
#include <cuda_fp16.h>
#include <cstdint>
#include <math.h>

#define BATCH 1024
#define DIMD  512
#define DM    1024
#define DI    2048
#define DTR   64
#define DS    16

// ---------------- static fp32 scratch ----------------
__device__ float g_cat [BATCH * DM];
__device__ float g_x   [BATCH * DM];
__device__ float g_alp [2 * 2 * BATCH * DIMD];  // align split-K partials
__device__ float g_h2  [2 * BATCH * 256];       // gate2 split-K partials
__device__ float g_xz  [BATCH * (2 * DI)];      // only z-half written/used
__device__ float g_xc  [BATCH * DI];
__device__ float g_dbcp[8 * BATCH * 96];        // x_proj split-K partials
__device__ float g_bcd [BATCH];
__device__ float g_mo2 [2 * BATCH * DM];        // out_proj split-K partials
__device__ float g_fcp [4 * BATCH * 256];       // fc split-K partials

// ---------------- static fp16 scratch ----------------
__device__ __half h_wimg[3 * DIMD * DIMD];
__device__ __half h_wtxt[3 * DIMD * DIMD];
__device__ __half h_wg1 [DIMD * DM];
__device__ __half h_wg2 [256 * DIMD];
__device__ __half h_winp[3 * (2 * DI) * DM];
__device__ __half h_wxp [3 * 96 * DI];
__device__ __half h_wdt [3 * DI * DTR];
__device__ __half h_wop [3 * DM * DI];
__device__ __half h_wfc [256 * DM];
__device__ __half h_feat[2 * BATCH * DIMD];
__device__ __half h_tB2 [2 * BATCH * DIMD];
__device__ __half h_cat [BATCH * DM];
__device__ __half h_h1  [BATCH * DIMD];
__device__ __half h_x   [BATCH * DM];
__device__ __half h_xc  [BATCH * DI];
__device__ __half h_dbc [BATCH * 96];
__device__ __half h_u   [BATCH * DI];

// ---------------- helpers ----------------
__device__ __forceinline__ float siluf(float x) { return x / (1.f + expf(-x)); }
__device__ __forceinline__ float softplusf_(float x) { return x > 20.f ? x : log1pf(expf(x)); }

enum { EPI_RELU = 1, EPI_INPROJ = 4, EPI_SSM = 5, EPI_PART = 6 };

__device__ __forceinline__ uint32_t smem_to_u32(const void* p) {
    uint32_t a;
    asm("{ .reg .u64 tmp; cvta.to.shared.u64 tmp, %1; cvt.u32.u64 %0, tmp; }"
        : "=r"(a) : "l"(p));
    return a;
}
#define SMEM_SWIZZLE_128B(byte_offset) \
    ((byte_offset) ^ (((byte_offset) >> 3) & 0x70))

__device__ __forceinline__ void mma_f16(float* c, const uint32_t* a, const uint32_t* b) {
    asm volatile(
        "mma.sync.aligned.m16n8k16.row.col.f32.f16.f16.f32 "
        "{%0,%1,%2,%3}, {%4,%5,%6,%7}, {%8,%9}, {%0,%1,%2,%3};"
        : "+f"(c[0]), "+f"(c[1]), "+f"(c[2]), "+f"(c[3])
        : "r"(a[0]), "r"(a[1]), "r"(a[2]), "r"(a[3]), "r"(b[0]), "r"(b[1]));
}
__device__ __forceinline__ void ldsm4(uint32_t* r, uint32_t addr) {
    asm volatile("ldmatrix.sync.aligned.m8n8.x4.shared.b16 {%0,%1,%2,%3}, [%4];"
                 : "=r"(r[0]), "=r"(r[1]), "=r"(r[2]), "=r"(r[3]) : "r"(addr));
}
__device__ __forceinline__ void cp_async16(uint32_t dst, const void* src, uint32_t sz) {
    asm volatile("cp.async.ca.shared.global [%0], [%1], 16, %2;"
                 :: "r"(dst), "l"(src), "r"(sz));
}

// ================= fp32 -> fp16 batch conversion =========================
#define NSEG 11
struct ConvArgs {
    const float4* src[NSEG];
    __half* dst[NSEG];
    int off[NSEG + 1];
};
__global__ void __launch_bounds__(256) conv_half_kernel(ConvArgs a, int total4)
{
    for (int idx = blockIdx.x * 256 + threadIdx.x; idx < total4;
         idx += gridDim.x * 256) {
        int seg = 0;
#pragma unroll
        for (int s = 1; s < NSEG; s++) if (idx >= a.off[s]) seg = s;
        int j = idx - a.off[seg];
        float4 v = a.src[seg][j];
        __half2* d = (__half2*)(a.dst[seg] + (size_t)j * 4);
        d[0] = __floats2half2_rn(v.x, v.y);
        d[1] = __floats2half2_rn(v.z, v.w);
    }
}

// ================= fp16 tensor-core GEMM =================================
// C = act(A[M,K] @ W[N,K]^T + bias)
// CTA 128x64, BK=64, 8 warps (warp tile 32x32), 4-stage cp.async pipeline,
// register fragment double-buffering, one __syncthreads per chunk.
// SMEM stage: A 16KB + B 8KB = 24KB; 4 stages = 96KB. 2 CTAs/SM target.
static constexpr int STAGE_BYTES = 24576;
static constexpr int MM_SMEM_BYTES = 4 * STAGE_BYTES;

template <int EPI>
__global__ void __launch_bounds__(256, 2) gemm_mma(
    const __half* __restrict__ A, const __half* __restrict__ Wm,
    const __half* __restrict__ Wm2, int Msplit,
    int M, int N, int K, int lda, int Ksplit,
    float* __restrict__ C, __half* __restrict__ C16,
    const float* __restrict__ bias, const float* __restrict__ bias2,
    float* __restrict__ X, __half* __restrict__ X16,
    const float* __restrict__ p0, const float* __restrict__ p1,
    const float* __restrict__ p2, const float* __restrict__ p3)
{
    extern __shared__ char smem[];
    const uint32_t sb = smem_to_u32(smem);
    const int tid = threadIdx.x;
    const int lane = tid & 31;
    const int wid = tid >> 5;
    const int wm = wid & 3;
    const int wn = wid >> 2;
    const int mBase = blockIdx.y * 128;
    const int nBase = blockIdx.x * 64;
    const int z = blockIdx.z;
    const int kOff = z * Ksplit;
    const int nch = Ksplit >> 6;

    const __half* Wsel = (mBase >= Msplit) ? Wm2 : Wm;
    const float* bsel  = (mBase >= Msplit) ? bias2 : bias;

    // ---- loader: 1536 16B segs (A:1024, B:512), 6 per thread ----
    const __half* gp[6];
    uint32_t dof[6], gsz[6];
#pragma unroll
    for (int j = 0; j < 6; j++) {
        int flat = tid * 6 + j;
        if (flat < 1024) {
            int arow = flat >> 3, acol = flat & 7;
            gp[j] = A + (size_t)(mBase + arow) * lda + kOff + acol * 8;
            dof[j] = SMEM_SWIZZLE_128B((uint32_t)arow * 128u + (uint32_t)acol * 16u);
            gsz[j] = 16;
        } else {
            int f2 = flat - 1024;
            int brow = f2 >> 3, bcol = f2 & 7;
            int grow = nBase + brow;
            gp[j] = Wsel + (size_t)(grow < N ? grow : 0) * K + kOff + bcol * 8;
            dof[j] = 16384u + SMEM_SWIZZLE_128B((uint32_t)brow * 128u + (uint32_t)bcol * 16u);
            gsz[j] = (grow < N) ? 16 : 0;
        }
    }

    // ldmatrix address components
    const uint32_t a_rowc = (uint32_t)(wm * 32 + (lane & 15));
    const uint32_t a_cb   = ((uint32_t)(lane >> 4)) * 16u;
    const uint32_t a_x    = (a_rowc & 7u) << 4;
    const uint32_t b_rowc = (uint32_t)(wn * 32 + (lane & 7) + ((lane >> 4) & 1) * 8);
    const uint32_t b_cb   = ((uint32_t)((lane >> 3) & 1)) * 16u;
    const uint32_t b_x    = ((uint32_t)(lane & 7)) << 4;

    float acc[2][4][4];
#pragma unroll
    for (int mf = 0; mf < 2; mf++)
#pragma unroll
        for (int nf = 0; nf < 4; nf++)
#pragma unroll
            for (int q = 0; q < 4; q++) acc[mf][nf][q] = 0.f;

    // ---- prologue: issue stages 0..2 ----
#pragma unroll
    for (int c = 0; c < 3; c++) {
        if (c < nch) {
            uint32_t base = sb + (uint32_t)c * STAGE_BYTES;
#pragma unroll
            for (int j = 0; j < 6; j++)
                cp_async16(base + dof[j], gp[j] + c * 64, gsz[j]);
        }
        asm volatile("cp.async.commit_group;");
    }

    for (int ch = 0; ch < nch; ch++) {
        asm volatile("cp.async.wait_group 2;");
        __syncthreads();

        // issue chunk ch+3 into stage (ch+3)&3 (safe: all warps past compute ch-1)
        const int nxt = ch + 3;
        if (nxt < nch) {
            uint32_t base = sb + (uint32_t)(nxt & 3) * STAGE_BYTES;
#pragma unroll
            for (int j = 0; j < 6; j++)
                cp_async16(base + dof[j], gp[j] + nxt * 64, gsz[j]);
        }
        asm volatile("cp.async.commit_group;");

        const uint32_t aAddr = sb + (uint32_t)(ch & 3) * STAGE_BYTES;
        const uint32_t bAddr = aAddr + 16384u;

        // register-double-buffered fragment pipeline over 4 k-steps
        uint32_t Af[2][2][4], Bf[2][2][4];
#pragma unroll
        for (int mf = 0; mf < 2; mf++)
            ldsm4(Af[0][mf], aAddr + (a_rowc + (uint32_t)mf * 16u) * 128u +
                             ((a_cb) ^ a_x));
#pragma unroll
        for (int p = 0; p < 2; p++)
            ldsm4(Bf[0][p], bAddr + (b_rowc + (uint32_t)p * 16u) * 128u +
                            ((b_cb) ^ b_x));
#pragma unroll
        for (int ks = 0; ks < 4; ks++) {
            const int cur = ks & 1, nst = (ks + 1) & 1;
            if (ks < 3) {
                const uint32_t kk = (uint32_t)(ks + 1) * 32u;
#pragma unroll
                for (int mf = 0; mf < 2; mf++)
                    ldsm4(Af[nst][mf], aAddr + (a_rowc + (uint32_t)mf * 16u) * 128u +
                                       ((kk + a_cb) ^ a_x));
#pragma unroll
                for (int p = 0; p < 2; p++)
                    ldsm4(Bf[nst][p], bAddr + (b_rowc + (uint32_t)p * 16u) * 128u +
                                      ((kk + b_cb) ^ b_x));
            }
#pragma unroll
            for (int mf = 0; mf < 2; mf++)
#pragma unroll
                for (int p = 0; p < 2; p++) {
                    mma_f16(acc[mf][p * 2 + 0], Af[cur][mf], &Bf[cur][p][0]);
                    mma_f16(acc[mf][p * 2 + 1], Af[cur][mf], &Bf[cur][p][2]);
                }
        }
    }

    // ---- epilogue ----
    float* Cz = C;
    if (EPI == EPI_PART) Cz = C + (size_t)z * M * N;
    const int mrow0 = mBase + wm * 32 + (lane >> 2);
    const int ncol00 = nBase + wn * 32 + (lane & 3) * 2;
    const int colOff[4] = {0, 8, 16, 24};
#pragma unroll
    for (int mf = 0; mf < 2; mf++) {
        const int r0 = mrow0 + mf * 16;
        const int r1 = r0 + 8;
#pragma unroll
        for (int nf = 0; nf < 4; nf++) {
            const int col = ncol00 + colOff[nf];
            if (col >= N) continue;
            float v0 = acc[mf][nf][0], v1 = acc[mf][nf][1];
            float v2 = acc[mf][nf][2], v3 = acc[mf][nf][3];

            if (EPI == EPI_PART) {
                float2 o0; o0.x = v0; o0.y = v1;
                float2 o1; o1.x = v2; o1.y = v3;
                *(float2*)(Cz + (size_t)r0 * N + col) = o0;
                *(float2*)(Cz + (size_t)r1 * N + col) = o1;
            } else if (EPI == EPI_INPROJ) {
                if (col < DI) {
                    // xc path: conv tap + bias + silu (xc-half of xz never stored)
                    float w0 = p0[col * 4 + 3], w1 = p0[(col + 1) * 4 + 3];
                    float cb0 = p1[col], cb1 = p1[col + 1];
                    float x0 = siluf(v0 * w0 + cb0), x1 = siluf(v1 * w1 + cb1);
                    float x2 = siluf(v2 * w0 + cb0), x3 = siluf(v3 * w1 + cb1);
                    float2 a0; a0.x = x0; a0.y = x1;
                    float2 a1; a1.x = x2; a1.y = x3;
                    *(float2*)(X + (size_t)r0 * DI + col) = a0;
                    *(float2*)(X + (size_t)r1 * DI + col) = a1;
                    *(__half2*)(X16 + (size_t)r0 * DI + col) = __floats2half2_rn(x0, x1);
                    *(__half2*)(X16 + (size_t)r1 * DI + col) = __floats2half2_rn(x2, x3);
                } else {
                    // z-half of xz
                    float2 o0; o0.x = v0; o0.y = v1;
                    float2 o1; o1.x = v2; o1.y = v3;
                    *(float2*)(C + (size_t)r0 * N + col) = o0;
                    *(float2*)(C + (size_t)r1 * N + col) = o1;
                }
            } else if (EPI == EPI_SSM) {
                float bb0 = bsel[col], bb1 = bsel[col + 1];
                float d0 = softplusf_(v0 + bb0), d1 = softplusf_(v1 + bb1);
                float d2 = softplusf_(v2 + bb0), d3 = softplusf_(v3 + bb1);
                float D0 = p3[col], D1 = p3[col + 1];
                float bc0 = p2[r0], bc1 = p2[r1];
                float2 xcA = *(const float2*)(p0 + (size_t)r0 * DI + col);
                float2 xcB = *(const float2*)(p0 + (size_t)r1 * DI + col);
                float2 zA = *(const float2*)(p1 + (size_t)r0 * (2 * DI) + DI + col);
                float2 zB = *(const float2*)(p1 + (size_t)r1 * (2 * DI) + DI + col);
                float u0 = xcA.x * (d0 * bc0 + D0) * siluf(zA.x);
                float u1 = xcA.y * (d1 * bc0 + D1) * siluf(zA.y);
                float u2 = xcB.x * (d2 * bc1 + D0) * siluf(zB.x);
                float u3 = xcB.y * (d3 * bc1 + D1) * siluf(zB.y);
                *(__half2*)(C16 + (size_t)r0 * N + col) = __floats2half2_rn(u0, u1);
                *(__half2*)(C16 + (size_t)r1 * N + col) = __floats2half2_rn(u2, u3);
            } else {  // EPI_RELU
                float bx = bsel[col], by = bsel[col + 1];
                v0 = fmaxf(v0 + bx, 0.f); v1 = fmaxf(v1 + by, 0.f);
                v2 = fmaxf(v2 + bx, 0.f); v3 = fmaxf(v3 + by, 0.f);
                if (C) {
                    float2 o0; o0.x = v0; o0.y = v1;
                    float2 o1; o1.x = v2; o1.y = v3;
                    *(float2*)(C + (size_t)r0 * N + col) = o0;
                    *(float2*)(C + (size_t)r1 * N + col) = o1;
                }
                if (C16) {
                    *(__half2*)(C16 + (size_t)r0 * N + col) = __floats2half2_rn(v0, v1);
                    *(__half2*)(C16 + (size_t)r1 * N + col) = __floats2half2_rn(v2, v3);
                }
            }
        }
    }
}

// ================= warp-per-row layernorm (with split-K reduce) ==========
__global__ void __launch_bounds__(256) ln_warp(
    float* __restrict__ out, __half* __restrict__ out16,
    const float* __restrict__ in, int S, size_t sstr,
    const float* __restrict__ res,
    const float* __restrict__ g, const float* __restrict__ b,
    int W, int ostride, int o16stride, int rows)
{
    const int gw = (blockIdx.x * blockDim.x + threadIdx.x) >> 5;
    const int lane = threadIdx.x & 31;
    if (gw >= rows) return;
    const int nv = W >> 7;
    float4 v[8];
    float s = 0.f, q = 0.f;
#pragma unroll 8
    for (int i = 0; i < nv; i++) {
        const int i4 = lane + i * 32;
        float4 t = ((const float4*)(in + (size_t)gw * W))[i4];
        for (int sp = 1; sp < S; sp++) {
            float4 t2 = ((const float4*)(in + sp * sstr + (size_t)gw * W))[i4];
            t.x += t2.x; t.y += t2.y; t.z += t2.z; t.w += t2.w;
        }
        if (res) {
            float4 r2 = ((const float4*)(res + (size_t)gw * W))[i4];
            t.x += r2.x; t.y += r2.y; t.z += r2.z; t.w += r2.w;
        }
        v[i] = t;
        s += t.x + t.y + t.z + t.w;
        q += t.x * t.x + t.y * t.y + t.z * t.z + t.w * t.w;
    }
#pragma unroll
    for (int o = 16; o > 0; o >>= 1) {
        s += __shfl_xor_sync(0xffffffffu, s, o);
        q += __shfl_xor_sync(0xffffffffu, q, o);
    }
    const float m = s / (float)W;
    const float r = rsqrtf(q / (float)W - m * m + 1e-5f);
#pragma unroll 8
    for (int i = 0; i < nv; i++) {
        const int i4 = lane + i * 32;
        float4 gg = ((const float4*)g)[i4];
        float4 bb = ((const float4*)b)[i4];
        float4 o;
        o.x = (v[i].x - m) * r * gg.x + bb.x;
        o.y = (v[i].y - m) * r * gg.y + bb.y;
        o.z = (v[i].z - m) * r * gg.z + bb.z;
        o.w = (v[i].w - m) * r * gg.w + bb.w;
        if (out) ((float4*)(out + (size_t)gw * ostride))[i4] = o;
        if (out16) {
            __half2* hp = (__half2*)(out16 + (size_t)gw * o16stride + i4 * 4);
            hp[0] = __floats2half2_rn(o.x, o.y);
            hp[1] = __floats2half2_rn(o.z, o.w);
        }
    }
}

// batched align LN with split-K reduce + bias + relu before stats.
// rows 0-1023 = img set, 1024-2047 = txt set (W=512)
__global__ void __launch_bounds__(256) ln_warp2(
    const float* __restrict__ in, int S, size_t sstr,
    const float* __restrict__ bias0, const float* __restrict__ bias1,
    float* __restrict__ out0, float* __restrict__ out1,
    __half* __restrict__ o16a, __half* __restrict__ o16b,
    const float* __restrict__ g0, const float* __restrict__ b0,
    const float* __restrict__ g1, const float* __restrict__ b1,
    int ostride, int o16stride)
{
    const int gw = (blockIdx.x * blockDim.x + threadIdx.x) >> 5;
    const int lane = threadIdx.x & 31;
    if (gw >= 2048) return;
    const int set = gw >> 10;
    const int rr = gw & 1023;
    const float* g = set ? g1 : g0;
    const float* b = set ? b1 : b0;
    const float* bv = set ? bias1 : bias0;
    float* out = set ? out1 : out0;
    __half* o16 = set ? o16b : o16a;
    float4 v[4];
    float s = 0.f, q = 0.f;
#pragma unroll
    for (int i = 0; i < 4; i++) {
        const int i4 = lane + i * 32;
        float4 t = ((const float4*)(in + (size_t)gw * 512))[i4];
        for (int sp = 1; sp < S; sp++) {
            float4 t2 = ((const float4*)(in + sp * sstr + (size_t)gw * 512))[i4];
            t.x += t2.x; t.y += t2.y; t.z += t2.z; t.w += t2.w;
        }
        float4 bb4 = ((const float4*)bv)[i4];
        t.x = fmaxf(t.x + bb4.x, 0.f);
        t.y = fmaxf(t.y + bb4.y, 0.f);
        t.z = fmaxf(t.z + bb4.z, 0.f);
        t.w = fmaxf(t.w + bb4.w, 0.f);
        v[i] = t;
        s += t.x + t.y + t.z + t.w;
        q += t.x * t.x + t.y * t.y + t.z * t.z + t.w * t.w;
    }
#pragma unroll
    for (int o = 16; o > 0; o >>= 1) {
        s += __shfl_xor_sync(0xffffffffu, s, o);
        q += __shfl_xor_sync(0xffffffffu, q, o);
    }
    const float m = s / 512.f;
    const float r = rsqrtf(q / 512.f - m * m + 1e-5f);
#pragma unroll
    for (int i = 0; i < 4; i++) {
        const int i4 = lane + i * 32;
        float4 gg = ((const float4*)g)[i4];
        float4 bb = ((const float4*)b)[i4];
        float4 o;
        o.x = (v[i].x - m) * r * gg.x + bb.x;
        o.y = (v[i].y - m) * r * gg.y + bb.y;
        o.z = (v[i].z - m) * r * gg.z + bb.z;
        o.w = (v[i].w - m) * r * gg.w + bb.w;
        if (out) ((float4*)(out + (size_t)rr * ostride))[i4] = o;
        if (o16) {
            __half2* hp = (__half2*)(o16 + (size_t)rr * o16stride + i4 * 4);
            hp[0] = __floats2half2_rn(o.x, o.y);
            hp[1] = __floats2half2_rn(o.z, o.w);
        }
    }
}

// ---------------- gate head (with gate2 split-K reduce + bias + relu) ----
__global__ void __launch_bounds__(128) gate_kernel(
    float* __restrict__ x, __half* __restrict__ x16,
    float* __restrict__ gate_out, const float* __restrict__ h2p,
    const float* __restrict__ b2,
    const float* __restrict__ cat, const float* __restrict__ w3,
    const float* __restrict__ b3)
{
    const int bi = blockIdx.x;
    const int t = threadIdx.x;
    float p0 = 0.f, p1 = 0.f;
    for (int i = t; i < 256; i += 128) {
        float hv = fmaxf(h2p[(size_t)bi * 256 + i]
                       + h2p[(size_t)BATCH * 256 + (size_t)bi * 256 + i]
                       + b2[i], 0.f);
        p0 += hv * w3[i];
        p1 += hv * w3[256 + i];
    }
    __shared__ float s0[4], s1[4];
    for (int o = 16; o > 0; o >>= 1) {
        p0 += __shfl_down_sync(0xffffffffu, p0, o);
        p1 += __shfl_down_sync(0xffffffffu, p1, o);
    }
    if ((t & 31) == 0) { s0[t >> 5] = p0; s1[t >> 5] = p1; }
    __syncthreads();
    __shared__ float g0s, g1s;
    if (t == 0) {
        float l0 = s0[0] + s0[1] + s0[2] + s0[3] + b3[0];
        float l1 = s1[0] + s1[1] + s1[2] + s1[3] + b3[1];
        float mx = fmaxf(l0, l1);
        float e0 = expf(l0 - mx), e1 = expf(l1 - mx);
        float inv = 1.f / (e0 + e1);
        g0s = e0 * inv; g1s = e1 * inv;
        gate_out[bi * 2 + 0] = g0s;
        gate_out[bi * 2 + 1] = g1s;
    }
    __syncthreads();
    const float g0 = g0s, g1 = g1s;
    const float* c = cat + (size_t)bi * DM;
    float* xo = x + (size_t)bi * DM;
    __half* xo16 = x16 + (size_t)bi * DM;
    for (int i = t; i < DM; i += 128) {
        float val = c[i] * (i < DIMD ? g0 : g1);
        xo[i] = val;
        xo16[i] = __float2half(val);
    }
}

// -------- x_proj split-K (S=8) reduce + Bc.Cc dot + fp16 convert --------
__global__ void __launch_bounds__(128) bcdot_kernel(
    float* __restrict__ bcd, __half* __restrict__ dbc16,
    const float* __restrict__ part)   // [8][BATCH][96]
{
    const int bi = blockIdx.x;
    const int t = threadIdx.x;
    __shared__ float sh[96];
    if (t < 96) {
        float s = 0.f;
#pragma unroll
        for (int sp = 0; sp < 8; sp++)
            s += part[(size_t)sp * BATCH * 96 + (size_t)bi * 96 + t];
        sh[t] = s;
        dbc16[(size_t)bi * 96 + t] = __float2half(s);
    }
    __syncthreads();
    if (t == 0) {
        float s = 0.f;
#pragma unroll
        for (int i = 0; i < DS; i++) s += sh[64 + i] * sh[80 + i];
        bcd[bi] = s;
    }
}

// ---------------- launch ----------------
static inline dim3 tgrid(int M, int N, int S = 1) {
    return dim3((N + 63) / 64, M / 128, S);
}
static constexpr int MBIG = 1 << 30;

extern "C" void kernel_launch(void* const* d_in, const int* in_sizes, int n_in,
                              void* d_out, int out_size)
{
    const float* image_features = (const float*)d_in[0];
    const float* text_features  = (const float*)d_in[1];
    const float* img_w    = (const float*)d_in[2];
    const float* img_b    = (const float*)d_in[3];
    const float* img_ln_g = (const float*)d_in[4];
    const float* img_ln_b = (const float*)d_in[5];
    const float* txt_w    = (const float*)d_in[6];
    const float* txt_b    = (const float*)d_in[7];
    const float* txt_ln_g = (const float*)d_in[8];
    const float* txt_ln_b = (const float*)d_in[9];
    const float* gate_w1  = (const float*)d_in[10];
    const float* gate_b1  = (const float*)d_in[11];
    const float* gate_w2  = (const float*)d_in[12];
    const float* gate_b2  = (const float*)d_in[13];
    const float* gate_w3  = (const float*)d_in[14];
    const float* gate_b3  = (const float*)d_in[15];
    const float* in_proj_w  = (const float*)d_in[16];
    const float* conv_w     = (const float*)d_in[17];
    const float* conv_b     = (const float*)d_in[18];
    const float* x_proj_w   = (const float*)d_in[19];
    const float* dt_proj_w  = (const float*)d_in[20];
    const float* dt_proj_b  = (const float*)d_in[21];
    /* d_in[22] = A_log: unused (L=1, h0=0) */
    const float* D_param    = (const float*)d_in[23];
    const float* out_proj_w = (const float*)d_in[24];
    const float* mnorm_g    = (const float*)d_in[25];
    const float* mnorm_b    = (const float*)d_in[26];
    const float* fc_w    = (const float*)d_in[27];
    const float* fc_b    = (const float*)d_in[28];
    const float* final_g = (const float*)d_in[29];
    const float* final_b = (const float*)d_in[30];

    float* out_fused = (float*)d_out;
    float* out_gate  = (float*)d_out + (size_t)BATCH * 256;

    float *cat, *x, *alp, *h2, *xz, *xc, *dbcp, *bcd, *mo2, *fcp;
    cudaGetSymbolAddress((void**)&cat,  g_cat);
    cudaGetSymbolAddress((void**)&x,    g_x);
    cudaGetSymbolAddress((void**)&alp,  g_alp);
    cudaGetSymbolAddress((void**)&h2,   g_h2);
    cudaGetSymbolAddress((void**)&xz,   g_xz);
    cudaGetSymbolAddress((void**)&xc,   g_xc);
    cudaGetSymbolAddress((void**)&dbcp, g_dbcp);
    cudaGetSymbolAddress((void**)&bcd,  g_bcd);
    cudaGetSymbolAddress((void**)&mo2,  g_mo2);
    cudaGetSymbolAddress((void**)&fcp,  g_fcp);

    __half *wimg, *wtxt, *wg1, *wg2, *winp, *wxp, *wdt, *wop, *wfc;
    __half *feat16, *tB216, *cat16, *h116, *x16, *xc16, *dbc16, *u16;
    cudaGetSymbolAddress((void**)&wimg, h_wimg);
    cudaGetSymbolAddress((void**)&wtxt, h_wtxt);
    cudaGetSymbolAddress((void**)&wg1,  h_wg1);
    cudaGetSymbolAddress((void**)&wg2,  h_wg2);
    cudaGetSymbolAddress((void**)&winp, h_winp);
    cudaGetSymbolAddress((void**)&wxp,  h_wxp);
    cudaGetSymbolAddress((void**)&wdt,  h_wdt);
    cudaGetSymbolAddress((void**)&wop,  h_wop);
    cudaGetSymbolAddress((void**)&wfc,  h_wfc);
    cudaGetSymbolAddress((void**)&feat16, h_feat);
    cudaGetSymbolAddress((void**)&tB216,  h_tB2);
    cudaGetSymbolAddress((void**)&cat16,  h_cat);
    cudaGetSymbolAddress((void**)&h116,   h_h1);
    cudaGetSymbolAddress((void**)&x16,    h_x);
    cudaGetSymbolAddress((void**)&xc16,   h_xc);
    cudaGetSymbolAddress((void**)&dbc16,  h_dbc);
    cudaGetSymbolAddress((void**)&u16,    h_u);

    cudaFuncSetAttribute(gemm_mma<EPI_RELU>,
                         cudaFuncAttributeMaxDynamicSharedMemorySize, MM_SMEM_BYTES);
    cudaFuncSetAttribute(gemm_mma<EPI_INPROJ>,
                         cudaFuncAttributeMaxDynamicSharedMemorySize, MM_SMEM_BYTES);
    cudaFuncSetAttribute(gemm_mma<EPI_SSM>,
                         cudaFuncAttributeMaxDynamicSharedMemorySize, MM_SMEM_BYTES);
    cudaFuncSetAttribute(gemm_mma<EPI_PART>,
                         cudaFuncAttributeMaxDynamicSharedMemorySize, MM_SMEM_BYTES);

    // ---- convert all weights + input features to fp16 (one kernel) ----
    {
        ConvArgs a;
        const float* srcs[NSEG] = {img_w, txt_w, gate_w1, gate_w2, in_proj_w,
                                   x_proj_w, dt_proj_w, out_proj_w, fc_w,
                                   image_features, text_features};
        __half* dsts[NSEG] = {wimg, wtxt, wg1, wg2, winp, wxp, wdt, wop, wfc,
                              feat16, feat16 + (size_t)BATCH * DIMD};
        int cnt4[NSEG] = {
            3 * DIMD * DIMD / 4, 3 * DIMD * DIMD / 4,
            DIMD * DM / 4, 256 * DIMD / 4,
            3 * (2 * DI) * DM / 4, 3 * 96 * DI / 4, 3 * DI * DTR / 4,
            3 * DM * DI / 4, 256 * DM / 4,
            BATCH * DIMD / 4, BATCH * DIMD / 4};
        int acc = 0;
        for (int i = 0; i < NSEG; i++) {
            a.src[i] = (const float4*)srcs[i];
            a.dst[i] = dsts[i];
            a.off[i] = acc;
            acc += cnt4[i];
        }
        a.off[NSEG] = acc;
        conv_half_kernel<<<2048, 256>>>(a, acc);
    }

    // ---- align: 3x batched (img+txt) gemm split-K2 -> LN (reduce+bias+relu fused) ----
    for (int i = 0; i < 3; i++) {
        gemm_mma<EPI_PART><<<tgrid(2 * BATCH, DIMD, 2), 256, MM_SMEM_BYTES>>>(
            (i == 0) ? feat16 : tB216,
            wimg + (size_t)i * DIMD * DIMD, wtxt + (size_t)i * DIMD * DIMD, BATCH,
            2 * BATCH, DIMD, DIMD, DIMD, DIMD / 2,
            alp, nullptr, nullptr, nullptr,
            nullptr, nullptr, nullptr, nullptr, nullptr, nullptr);
        if (i < 2) {
            ln_warp2<<<256, 256>>>(alp, 2, (size_t)2 * BATCH * DIMD,
                                   img_b + (size_t)i * DIMD, txt_b + (size_t)i * DIMD,
                                   nullptr, nullptr,
                                   tB216, tB216 + (size_t)BATCH * DIMD,
                                   img_ln_g + (size_t)i * DIMD, img_ln_b + (size_t)i * DIMD,
                                   txt_ln_g + (size_t)i * DIMD, txt_ln_b + (size_t)i * DIMD,
                                   DIMD, DIMD);
        } else {
            ln_warp2<<<256, 256>>>(alp, 2, (size_t)2 * BATCH * DIMD,
                                   img_b + (size_t)i * DIMD, txt_b + (size_t)i * DIMD,
                                   cat, cat + DIMD,
                                   cat16, cat16 + DIMD,
                                   img_ln_g + (size_t)i * DIMD, img_ln_b + (size_t)i * DIMD,
                                   txt_ln_g + (size_t)i * DIMD, txt_ln_b + (size_t)i * DIMD,
                                   DM, DM);
        }
    }

    // ---- gate MLP -> softmax -> build x ----
    gemm_mma<EPI_RELU><<<tgrid(BATCH, DIMD), 256, MM_SMEM_BYTES>>>(
        cat16, wg1, nullptr, MBIG, BATCH, DIMD, DM, DM, DM,
        nullptr, h116, gate_b1, nullptr,
        nullptr, nullptr, nullptr, nullptr, nullptr, nullptr);
    gemm_mma<EPI_PART><<<tgrid(BATCH, 256, 2), 256, MM_SMEM_BYTES>>>(
        h116, wg2, nullptr, MBIG, BATCH, 256, DIMD, DIMD, DIMD / 2,
        h2, nullptr, nullptr, nullptr,
        nullptr, nullptr, nullptr, nullptr, nullptr, nullptr);
    gate_kernel<<<BATCH, 128>>>(x, x16, out_gate, h2, gate_b2, cat, gate_w3, gate_b3);

    // ---- 3 mamba layers (L=1 collapsed) ----
    for (int l = 0; l < 3; l++) {
        gemm_mma<EPI_INPROJ><<<tgrid(BATCH, 2 * DI), 256, MM_SMEM_BYTES>>>(
            x16, winp + (size_t)l * (2 * DI) * DM, nullptr, MBIG,
            BATCH, 2 * DI, DM, DM, DM,
            xz, nullptr, nullptr, nullptr,
            xc, xc16, conv_w + (size_t)l * DI * 4, conv_b + (size_t)l * DI,
            nullptr, nullptr);
        // x_proj split-K S=8 -> partials, reduce in bcdot
        gemm_mma<EPI_PART><<<tgrid(BATCH, 96, 8), 256, MM_SMEM_BYTES>>>(
            xc16, wxp + (size_t)l * 96 * DI, nullptr, MBIG,
            BATCH, 96, DI, DI, DI / 8,
            dbcp, nullptr, nullptr, nullptr,
            nullptr, nullptr, nullptr, nullptr, nullptr, nullptr);
        bcdot_kernel<<<BATCH, 128>>>(bcd, dbc16, dbcp);
        gemm_mma<EPI_SSM><<<tgrid(BATCH, DI), 256, MM_SMEM_BYTES>>>(
            dbc16, wdt + (size_t)l * DI * DTR, nullptr, MBIG,
            BATCH, DI, DTR, 96, DTR,
            nullptr, u16, dt_proj_b + (size_t)l * DI, nullptr,
            nullptr, nullptr, xc, xz, bcd, D_param + (size_t)l * DI);
        // out_proj split-K S=2 -> partials, reduce fused in residual LN
        gemm_mma<EPI_PART><<<tgrid(BATCH, DM, 2), 256, MM_SMEM_BYTES>>>(
            u16, wop + (size_t)l * DM * DI, nullptr, MBIG,
            BATCH, DM, DI, DI, DI / 2,
            mo2, nullptr, nullptr, nullptr,
            nullptr, nullptr, nullptr, nullptr, nullptr, nullptr);
        ln_warp<<<128, 256>>>(x, x16, mo2, 2, (size_t)BATCH * DM, x,
                              mnorm_g + (size_t)l * DM, mnorm_b + (size_t)l * DM,
                              DM, DM, DM, BATCH);
    }

    // ---- final fc (split-K S=4) + LN (reduce fused) -> fused output ----
    gemm_mma<EPI_PART><<<tgrid(BATCH, 256, 4), 256, MM_SMEM_BYTES>>>(
        x16, wfc, nullptr, MBIG, BATCH, 256, DM, DM, DM / 4,
        fcp, nullptr, nullptr, nullptr,
        nullptr, nullptr, nullptr, nullptr, nullptr, nullptr);
    ln_warp<<<128, 256>>>(out_fused, nullptr, fcp, 4, (size_t)BATCH * 256, nullptr,
                          final_g, final_b, 256, 256, 256, BATCH);
}